// round 8
// baseline (speedup 1.0000x reference)
#include <cuda_runtime.h>
#include <cstdint>

// ---------------------------------------------------------------------------
// ChainGNN: 3-layer GAT (heads 4/2/1, ch 32/32/16), N=50000, E=800000 (+self loops)
// CSR-fused design + high-intensity fp32 GEMM (256x64 tile, 8x8 per thread).
// ---------------------------------------------------------------------------

constexpr int NN = 50000;
constexpr int EMAX = 800000;
constexpr float SLOPE = 0.2f;

// Scratch (device globals; allocation is forbidden)
__device__ float g_h[NN * 128];       // post-GEMM features of current layer
__device__ float g_y1[NN * 128];      // layer1 activations
__device__ float g_y2[NN * 64];       // layer2 activations
__device__ float g_as[NN * 4];
__device__ float g_ad[NN * 4];
__device__ int   g_cnt[NN];
__device__ int   g_off[NN + 1];
__device__ int   g_cursor[NN];
__device__ int   g_csr_src[EMAX];

__device__ __forceinline__ float leaky(float v) { return v > 0.f ? v : SLOPE * v; }

// ---------------------------------------------------------------------------
// GEMM: O[n, outc] = X[n, K] @ W[K, outc].
// 256x64 tile, BK=16, 256 threads, 8x8 outputs/thread (64 FFMA per k-step).
// X tile stored k-major (transposed) so compute loads are conflict-free LDS.128.
// ---------------------------------------------------------------------------
__global__ void __launch_bounds__(256, 2)
gemm_kernel(const float* __restrict__ X, const float* __restrict__ W,
            float* __restrict__ O, int n, int K, int outc) {
    constexpr int BM = 256, BN = 64, BK = 16, TM = 8, TN = 8;
    __shared__ float Xs[BK][BM];   // 16 KB, k-major
    __shared__ float Ws[BK][BN];   // 4 KB
    int t = threadIdx.x;           // 256 threads
    int row0 = blockIdx.y * BM;
    int col0 = blockIdx.x * BN;
    int tidx = t & 7;              // 8 col groups
    int tidy = t >> 3;             // 32 row groups
    float acc[TM][TN] = {};

    for (int kk = 0; kk < K; kk += BK) {
        // X tile: 1024 float4 loads, 4 per thread. m = f/4, kseg = (f%4)*4.
        // Warp covers 8 rows x 64B contiguous-per-row -> coalesced.
        #pragma unroll
        for (int i = 0; i < 4; i++) {
            int f = t + i * 256;
            int m = f >> 2;
            int kseg = (f & 3) * 4;
            int gr = row0 + m;
            float4 v = make_float4(0.f, 0.f, 0.f, 0.f);
            if (gr < n)
                v = *reinterpret_cast<const float4*>(&X[(size_t)gr * K + kk + kseg]);
            Xs[kseg + 0][m] = v.x;
            Xs[kseg + 1][m] = v.y;
            Xs[kseg + 2][m] = v.z;
            Xs[kseg + 3][m] = v.w;
        }
        // W tile: 256 float4 loads, 1 per thread.
        {
            int wr = t >> 4;
            int wc = (t & 15) * 4;
            int gc = col0 + wc;
            float4 v = make_float4(0.f, 0.f, 0.f, 0.f);
            if (gc < outc)
                v = *reinterpret_cast<const float4*>(&W[(size_t)(kk + wr) * outc + gc]);
            *reinterpret_cast<float4*>(&Ws[wr][wc]) = v;  // zeros if OOB
        }
        __syncthreads();
        #pragma unroll
        for (int k = 0; k < BK; k++) {
            float4 a0 = *reinterpret_cast<const float4*>(&Xs[k][tidy * TM]);
            float4 a1 = *reinterpret_cast<const float4*>(&Xs[k][tidy * TM + 4]);
            float4 b0 = *reinterpret_cast<const float4*>(&Ws[k][tidx * TN]);
            float4 b1 = *reinterpret_cast<const float4*>(&Ws[k][tidx * TN + 4]);
            float av[TM] = {a0.x, a0.y, a0.z, a0.w, a1.x, a1.y, a1.z, a1.w};
            float bv[TN] = {b0.x, b0.y, b0.z, b0.w, b1.x, b1.y, b1.z, b1.w};
            #pragma unroll
            for (int i = 0; i < TM; i++)
                #pragma unroll
                for (int j = 0; j < TN; j++) acc[i][j] += av[i] * bv[j];
        }
        __syncthreads();
    }
    #pragma unroll
    for (int i = 0; i < TM; i++) {
        int gr = row0 + tidy * TM + i;
        if (gr >= n) continue;
        int gc = col0 + tidx * TN;
        if (gc < outc) {
            *reinterpret_cast<float4*>(&O[(size_t)gr * outc + gc]) =
                make_float4(acc[i][0], acc[i][1], acc[i][2], acc[i][3]);
            *reinterpret_cast<float4*>(&O[(size_t)gr * outc + gc + 4]) =
                make_float4(acc[i][4], acc[i][5], acc[i][6], acc[i][7]);
        }
    }
}

// ---------------------------------------------------------------------------
// CSR build: histogram -> scan -> scatter
// ---------------------------------------------------------------------------
__global__ void hist_kernel(const int* __restrict__ ei, int E, int* __restrict__ cnt) {
    int e = blockIdx.x * blockDim.x + threadIdx.x;
    if (e < E) atomicAdd(&cnt[ei[E + e]], 1);
}

// single-block exclusive scan over NN counters
__global__ void scan_kernel(const int* __restrict__ cnt, int* __restrict__ off,
                            int* __restrict__ cursor) {
    __shared__ int part[1024];
    int t = threadIdx.x;
    constexpr int PER = (NN + 1023) / 1024;   // 49
    int base = t * PER;
    int sum = 0;
    for (int i = 0; i < PER; i++) {
        int idx = base + i;
        sum += (idx < NN) ? cnt[idx] : 0;
    }
    part[t] = sum;
    __syncthreads();
    for (int o = 1; o < 1024; o <<= 1) {
        int other = (t >= o) ? part[t - o] : 0;
        __syncthreads();
        part[t] += other;
        __syncthreads();
    }
    int run = part[t] - sum;   // exclusive chunk offset
    for (int i = 0; i < PER; i++) {
        int idx = base + i;
        if (idx < NN) {
            off[idx] = run;
            cursor[idx] = run;
            run += cnt[idx];
        }
    }
    if (t == 1023) off[NN] = part[1023];
}

__global__ void build_kernel(const int* __restrict__ ei, int E,
                             int* __restrict__ cursor, int* __restrict__ csr_src) {
    int e = blockIdx.x * blockDim.x + threadIdx.x;
    if (e >= E) return;
    int d = ei[E + e];
    int pos = atomicAdd(&cursor[d], 1);
    csr_src[pos] = ei[e];
}

// ---------------------------------------------------------------------------
// Per-node attention scalars: as = <h, a_src>, ad = <h, a_dst>. One warp/node.
// ---------------------------------------------------------------------------
template <int H, int C>
__global__ void attn_node_kernel(const float* __restrict__ h,
                                 const float* __restrict__ a_src,
                                 const float* __restrict__ a_dst,
                                 float* __restrict__ as_, float* __restrict__ ad_) {
    int node = blockIdx.x * (blockDim.x >> 5) + (threadIdx.x >> 5);
    if (node >= NN) return;
    int lane = threadIdx.x & 31;
    const float* hr = h + (size_t)node * H * C;
    #pragma unroll
    for (int hh = 0; hh < H; hh++) {
        float s = 0.f, d = 0.f;
        for (int c = lane; c < C; c += 32) {
            float v = hr[hh * C + c];
            s += v * a_src[hh * C + c];
            d += v * a_dst[hh * C + c];
        }
        #pragma unroll
        for (int o = 16; o > 0; o >>= 1) {
            s += __shfl_xor_sync(0xffffffffu, s, o);
            d += __shfl_xor_sync(0xffffffffu, d, o);
        }
        if (lane == 0) {
            as_[node * H + hh] = s;
            ad_[node * H + hh] = d;
        }
    }
}

// ---------------------------------------------------------------------------
// Fused aggregation: per dst node, online-softmax over its in-edges + self loop.
// H*C/4 lanes per node, each owns a float4 slice. No atomics, all in registers.
// ---------------------------------------------------------------------------
template <int H, int C, int RELU>
__global__ void aggregate_kernel(const int* __restrict__ off,
                                 const int* __restrict__ csr_src,
                                 const float* __restrict__ h,
                                 const float* __restrict__ as_,
                                 const float* __restrict__ ad_,
                                 const float* __restrict__ bias,
                                 float* __restrict__ y) {
    constexpr int HC = H * C;
    constexpr int LPN = HC / 4;         // lanes per node
    constexpr int NPB = 128 / LPN;      // nodes per 128-thread block
    int t = threadIdx.x;
    int sub = t % LPN;
    int node = blockIdx.x * NPB + t / LPN;
    if (node >= NN) return;

    int fo = sub * 4;
    int hh = fo / C;
    float ad_d = ad_[node * H + hh];

    // self loop seeds the online softmax
    float m = leaky(as_[node * H + hh] + ad_d);
    float den = 1.f;
    float4 acc = *reinterpret_cast<const float4*>(&h[(size_t)node * HC + fo]);

    int beg = off[node], end = off[node + 1];
    #pragma unroll 2
    for (int idx = beg; idx < end; idx++) {
        int s = csr_src[idx];
        float l = leaky(as_[s * H + hh] + ad_d);
        float4 hv = *reinterpret_cast<const float4*>(&h[(size_t)s * HC + fo]);
        float nm = fmaxf(m, l);
        float scale = __expf(m - nm);
        float p = __expf(l - nm);
        acc.x = acc.x * scale + p * hv.x;
        acc.y = acc.y * scale + p * hv.y;
        acc.z = acc.z * scale + p * hv.z;
        acc.w = acc.w * scale + p * hv.w;
        den = den * scale + p;
        m = nm;
    }

    float iv = 1.f / (den + 1e-16f);
    float4 bv = *reinterpret_cast<const float4*>(&bias[fo]);
    float4 o;
    o.x = acc.x * iv + bv.x;
    o.y = acc.y * iv + bv.y;
    o.z = acc.z * iv + bv.z;
    o.w = acc.w * iv + bv.w;
    if (RELU) {
        o.x = fmaxf(o.x, 0.f); o.y = fmaxf(o.y, 0.f);
        o.z = fmaxf(o.z, 0.f); o.w = fmaxf(o.w, 0.f);
    }
    *reinterpret_cast<float4*>(&y[(size_t)node * HC + fo]) = o;
}

// ---------------------------------------------------------------------------
// Launch
// ---------------------------------------------------------------------------
template <int H, int C, int RELU>
static void run_layer(const float* x, int K,
                      const float* W, const float* asrc, const float* adst, const float* bias,
                      float* h, float* pas, float* pad,
                      const int* off, const int* csr_src, float* y) {
    constexpr int OC = H * C;
    dim3 ggrid((OC + 63) / 64, (NN + 255) / 256);
    gemm_kernel<<<ggrid, 256>>>(x, W, h, NN, K, OC);
    attn_node_kernel<H, C><<<(NN + 3) / 4, 128>>>(h, asrc, adst, pas, pad);
    constexpr int NPB = 128 / (OC / 4);
    aggregate_kernel<H, C, RELU><<<(NN + NPB - 1) / NPB, 128>>>(
        off, csr_src, h, pas, pad, bias, y);
}

extern "C" void kernel_launch(void* const* d_in, const int* in_sizes, int n_in,
                              void* d_out, int out_size) {
    const float* x = (const float*)d_in[0];
    const int* ei = (const int*)d_in[1];           // int32 (JAX x64 disabled)
    const float* W1 = (const float*)d_in[2];
    const float* as1 = (const float*)d_in[3];
    const float* ad1 = (const float*)d_in[4];
    const float* b1 = (const float*)d_in[5];
    const float* W2 = (const float*)d_in[6];
    const float* as2 = (const float*)d_in[7];
    const float* ad2 = (const float*)d_in[8];
    const float* b2 = (const float*)d_in[9];
    const float* W3 = (const float*)d_in[10];
    const float* as3 = (const float*)d_in[11];
    const float* ad3 = (const float*)d_in[12];
    const float* b3 = (const float*)d_in[13];
    int E = in_sizes[1] / 2;

    float *h, *y1, *y2, *pas, *pad;
    int *cnt, *off, *cursor, *csr_src;
    cudaGetSymbolAddress((void**)&h, g_h);
    cudaGetSymbolAddress((void**)&y1, g_y1);
    cudaGetSymbolAddress((void**)&y2, g_y2);
    cudaGetSymbolAddress((void**)&pas, g_as);
    cudaGetSymbolAddress((void**)&pad, g_ad);
    cudaGetSymbolAddress((void**)&cnt, g_cnt);
    cudaGetSymbolAddress((void**)&off, g_off);
    cudaGetSymbolAddress((void**)&cursor, g_cursor);
    cudaGetSymbolAddress((void**)&csr_src, g_csr_src);

    // Build CSR (group edges by destination) once; reused by all 3 layers.
    cudaMemsetAsync(cnt, 0, NN * sizeof(int));
    hist_kernel<<<(E + 255) / 256, 256>>>(ei, E, cnt);
    scan_kernel<<<1, 1024>>>(cnt, off, cursor);
    build_kernel<<<(E + 255) / 256, 256>>>(ei, E, cursor, csr_src);

    // Layer 1: in 128 -> 4 heads x 32, concat (128), relu
    run_layer<4, 32, 1>(x, 128, W1, as1, ad1, b1, h, pas, pad, off, csr_src, y1);
    // Layer 2: in 128 -> 2 heads x 32, concat (64), relu
    run_layer<2, 32, 1>(y1, 128, W2, as2, ad2, b2, h, pas, pad, off, csr_src, y2);
    // Layer 3: in 64 -> 1 head x 16, mean over 1 head == identity, no relu
    run_layer<1, 16, 0>(y2, 64, W3, as3, ad3, b3, h, pas, pad, off, csr_src, (float*)d_out);
}

// round 10
// speedup vs baseline: 1.0635x; 1.0635x over previous
#include <cuda_runtime.h>
#include <cstdint>

// ---------------------------------------------------------------------------
// ChainGNN: 3-layer GAT (heads 4/2/1, ch 32/32/16), N=50000, E=800000 (+self loops)
// CSR-fused design + 3xTF32 tensor-core GEMM (mma.sync m16n8k8).
// ---------------------------------------------------------------------------

constexpr int NN = 50000;
constexpr int EMAX = 800000;
constexpr float SLOPE = 0.2f;

// Scratch (device globals; allocation is forbidden)
__device__ float g_h[NN * 128];       // post-GEMM features of current layer
__device__ float g_y1[NN * 128];      // layer1 activations
__device__ float g_y2[NN * 64];       // layer2 activations
__device__ float g_as[NN * 4];
__device__ float g_ad[NN * 4];
__device__ int   g_cnt[NN];
__device__ int   g_off[NN + 1];
__device__ int   g_cursor[NN];
__device__ int   g_csr_src[EMAX];

__device__ __forceinline__ float leaky(float v) { return v > 0.f ? v : SLOPE * v; }

__device__ __forceinline__ uint32_t f2tf32(float x) {
    uint32_t r;
    asm("cvt.rna.tf32.f32 %0, %1;" : "=r"(r) : "f"(x));
    return r;
}

#define MMA_TF32(C, A, B)                                                     \
    asm volatile("mma.sync.aligned.m16n8k8.row.col.f32.tf32.tf32.f32 "        \
                 "{%0,%1,%2,%3}, {%4,%5,%6,%7}, {%8,%9}, {%0,%1,%2,%3};"      \
                 : "+f"(C[0]), "+f"(C[1]), "+f"(C[2]), "+f"(C[3])             \
                 : "r"(A[0]), "r"(A[1]), "r"(A[2]), "r"(A[3]),                \
                   "r"(B[0]), "r"(B[1]))

// ---------------------------------------------------------------------------
// GEMM: O[n, outc] = X[n, K] @ W[K, outc].  3xTF32 tensor cores.
// Block 128x64, 256 threads (8 warps as 4Mx2N), warp tile 32x32, BK=16.
// hi/lo tf32 planes staged in shared; pad strides 20/72 -> conflict-free gathers.
// ---------------------------------------------------------------------------
__global__ void __launch_bounds__(256)
gemm_kernel(const float* __restrict__ X, const float* __restrict__ W,
            float* __restrict__ O, int n, int K, int outc) {
    constexpr int BM = 128, BN = 64, BK = 16;
    constexpr int XS = 20;   // Xs row stride (16 + 4 pad)
    constexpr int WS = 72;   // Ws row stride (64 + 8 pad)
    __shared__ uint32_t XsH[BM * XS], XsL[BM * XS];
    __shared__ uint32_t WsH[BK * WS], WsL[BK * WS];

    int t = threadIdx.x;
    int lane = t & 31;
    int wid = t >> 5;
    int warp_m = wid & 3;      // 0..3
    int warp_n = wid >> 2;     // 0..1
    int row0 = blockIdx.y * BM;
    int col0 = blockIdx.x * BN;

    float acc[2][4][4] = {};   // [mtile][ntile][frag]

    for (int kk = 0; kk < K; kk += BK) {
        // X tile: 128 rows x 16 k = 512 float4s, 2 per thread
        #pragma unroll
        for (int i = 0; i < 2; i++) {
            int f = t + i * 256;
            int m = f >> 2;
            int kseg = (f & 3) * 4;
            int gr = row0 + m;
            float4 v = make_float4(0.f, 0.f, 0.f, 0.f);
            if (gr < n)
                v = *reinterpret_cast<const float4*>(&X[(size_t)gr * K + kk + kseg]);
            float xv[4] = {v.x, v.y, v.z, v.w};
            #pragma unroll
            for (int j = 0; j < 4; j++) {
                uint32_t hi = f2tf32(xv[j]);
                float lo = xv[j] - __uint_as_float(hi);
                XsH[m * XS + kseg + j] = hi;
                XsL[m * XS + kseg + j] = f2tf32(lo);
            }
        }
        // W tile: 16 x 64 = 1024 floats, 1 float4 per thread
        {
            int wr = t >> 4;
            int wc = (t & 15) * 4;
            int gc = col0 + wc;
            float4 v = make_float4(0.f, 0.f, 0.f, 0.f);
            if (gc < outc)
                v = *reinterpret_cast<const float4*>(&W[(size_t)(kk + wr) * outc + gc]);
            float wv[4] = {v.x, v.y, v.z, v.w};
            #pragma unroll
            for (int j = 0; j < 4; j++) {
                uint32_t hi = f2tf32(wv[j]);
                float lo = wv[j] - __uint_as_float(hi);
                WsH[wr * WS + wc + j] = hi;
                WsL[wr * WS + wc + j] = f2tf32(lo);
            }
        }
        __syncthreads();

        #pragma unroll
        for (int ks = 0; ks < 2; ks++) {
            int k0 = ks * 8;
            // A fragments (hi/lo) for 2 M tiles
            uint32_t aH[2][4], aL[2][4];
            #pragma unroll
            for (int mt = 0; mt < 2; mt++) {
                int r = warp_m * 32 + mt * 16 + (lane >> 2);
                int c = k0 + (lane & 3);
                aH[mt][0] = XsH[r * XS + c];           aL[mt][0] = XsL[r * XS + c];
                aH[mt][1] = XsH[(r + 8) * XS + c];     aL[mt][1] = XsL[(r + 8) * XS + c];
                aH[mt][2] = XsH[r * XS + c + 4];       aL[mt][2] = XsL[r * XS + c + 4];
                aH[mt][3] = XsH[(r + 8) * XS + c + 4]; aL[mt][3] = XsL[(r + 8) * XS + c + 4];
            }
            // B fragments (hi/lo) for 4 N tiles
            uint32_t bH[4][2], bL[4][2];
            #pragma unroll
            for (int nt = 0; nt < 4; nt++) {
                int cc = warp_n * 32 + nt * 8 + (lane >> 2);
                int rr = k0 + (lane & 3);
                bH[nt][0] = WsH[rr * WS + cc];       bL[nt][0] = WsL[rr * WS + cc];
                bH[nt][1] = WsH[(rr + 4) * WS + cc]; bL[nt][1] = WsL[(rr + 4) * WS + cc];
            }
            #pragma unroll
            for (int mt = 0; mt < 2; mt++)
                #pragma unroll
                for (int nt = 0; nt < 4; nt++) {
                    MMA_TF32(acc[mt][nt], aH[mt], bH[nt]);  // hi*hi
                    MMA_TF32(acc[mt][nt], aH[mt], bL[nt]);  // hi*lo
                    MMA_TF32(acc[mt][nt], aL[mt], bH[nt]);  // lo*hi
                }
        }
        __syncthreads();
    }

    // Epilogue: each fragment -> two float2 stores
    #pragma unroll
    for (int mt = 0; mt < 2; mt++)
        #pragma unroll
        for (int nt = 0; nt < 4; nt++) {
            int gr0 = row0 + warp_m * 32 + mt * 16 + (lane >> 2);
            int gc = col0 + warp_n * 32 + nt * 8 + (lane & 3) * 2;
            if (gc < outc) {
                if (gr0 < n)
                    *reinterpret_cast<float2*>(&O[(size_t)gr0 * outc + gc]) =
                        make_float2(acc[mt][nt][0], acc[mt][nt][1]);
                if (gr0 + 8 < n)
                    *reinterpret_cast<float2*>(&O[(size_t)(gr0 + 8) * outc + gc]) =
                        make_float2(acc[mt][nt][2], acc[mt][nt][3]);
            }
        }
}

// ---------------------------------------------------------------------------
// CSR build: histogram -> scan -> scatter
// ---------------------------------------------------------------------------
__global__ void hist_kernel(const int* __restrict__ ei, int E, int* __restrict__ cnt) {
    int e = blockIdx.x * blockDim.x + threadIdx.x;
    if (e < E) atomicAdd(&cnt[ei[E + e]], 1);
}

__global__ void scan_kernel(const int* __restrict__ cnt, int* __restrict__ off,
                            int* __restrict__ cursor) {
    __shared__ int part[1024];
    int t = threadIdx.x;
    constexpr int PER = (NN + 1023) / 1024;   // 49
    int base = t * PER;
    int sum = 0;
    for (int i = 0; i < PER; i++) {
        int idx = base + i;
        sum += (idx < NN) ? cnt[idx] : 0;
    }
    part[t] = sum;
    __syncthreads();
    for (int o = 1; o < 1024; o <<= 1) {
        int other = (t >= o) ? part[t - o] : 0;
        __syncthreads();
        part[t] += other;
        __syncthreads();
    }
    int run = part[t] - sum;
    for (int i = 0; i < PER; i++) {
        int idx = base + i;
        if (idx < NN) {
            off[idx] = run;
            cursor[idx] = run;
            run += cnt[idx];
        }
    }
    if (t == 1023) off[NN] = part[1023];
}

__global__ void build_kernel(const int* __restrict__ ei, int E,
                             int* __restrict__ cursor, int* __restrict__ csr_src) {
    int e = blockIdx.x * blockDim.x + threadIdx.x;
    if (e >= E) return;
    int d = ei[E + e];
    int pos = atomicAdd(&cursor[d], 1);
    csr_src[pos] = ei[e];
}

// ---------------------------------------------------------------------------
// Per-node attention scalars: as = <h, a_src>, ad = <h, a_dst>. One warp/node.
// ---------------------------------------------------------------------------
template <int H, int C>
__global__ void attn_node_kernel(const float* __restrict__ h,
                                 const float* __restrict__ a_src,
                                 const float* __restrict__ a_dst,
                                 float* __restrict__ as_, float* __restrict__ ad_) {
    int node = blockIdx.x * (blockDim.x >> 5) + (threadIdx.x >> 5);
    if (node >= NN) return;
    int lane = threadIdx.x & 31;
    const float* hr = h + (size_t)node * H * C;
    #pragma unroll
    for (int hh = 0; hh < H; hh++) {
        float s = 0.f, d = 0.f;
        for (int c = lane; c < C; c += 32) {
            float v = hr[hh * C + c];
            s += v * a_src[hh * C + c];
            d += v * a_dst[hh * C + c];
        }
        #pragma unroll
        for (int o = 16; o > 0; o >>= 1) {
            s += __shfl_xor_sync(0xffffffffu, s, o);
            d += __shfl_xor_sync(0xffffffffu, d, o);
        }
        if (lane == 0) {
            as_[node * H + hh] = s;
            ad_[node * H + hh] = d;
        }
    }
}

// ---------------------------------------------------------------------------
// Fused aggregation: per dst node, online-softmax over its in-edges + self loop.
// ---------------------------------------------------------------------------
template <int H, int C, int RELU>
__global__ void aggregate_kernel(const int* __restrict__ off,
                                 const int* __restrict__ csr_src,
                                 const float* __restrict__ h,
                                 const float* __restrict__ as_,
                                 const float* __restrict__ ad_,
                                 const float* __restrict__ bias,
                                 float* __restrict__ y) {
    constexpr int HC = H * C;
    constexpr int LPN = HC / 4;         // lanes per node
    constexpr int NPB = 128 / LPN;      // nodes per 128-thread block
    int t = threadIdx.x;
    int sub = t % LPN;
    int node = blockIdx.x * NPB + t / LPN;
    if (node >= NN) return;

    int fo = sub * 4;
    int hh = fo / C;
    float ad_d = ad_[node * H + hh];

    float m = leaky(as_[node * H + hh] + ad_d);
    float den = 1.f;
    float4 acc = *reinterpret_cast<const float4*>(&h[(size_t)node * HC + fo]);

    int beg = off[node], end = off[node + 1];
    #pragma unroll 2
    for (int idx = beg; idx < end; idx++) {
        int s = csr_src[idx];
        float l = leaky(as_[s * H + hh] + ad_d);
        float4 hv = *reinterpret_cast<const float4*>(&h[(size_t)s * HC + fo]);
        float nm = fmaxf(m, l);
        float scale = __expf(m - nm);
        float p = __expf(l - nm);
        acc.x = acc.x * scale + p * hv.x;
        acc.y = acc.y * scale + p * hv.y;
        acc.z = acc.z * scale + p * hv.z;
        acc.w = acc.w * scale + p * hv.w;
        den = den * scale + p;
        m = nm;
    }

    float iv = 1.f / (den + 1e-16f);
    float4 bv = *reinterpret_cast<const float4*>(&bias[fo]);
    float4 o;
    o.x = acc.x * iv + bv.x;
    o.y = acc.y * iv + bv.y;
    o.z = acc.z * iv + bv.z;
    o.w = acc.w * iv + bv.w;
    if (RELU) {
        o.x = fmaxf(o.x, 0.f); o.y = fmaxf(o.y, 0.f);
        o.z = fmaxf(o.z, 0.f); o.w = fmaxf(o.w, 0.f);
    }
    *reinterpret_cast<float4*>(&y[(size_t)node * HC + fo]) = o;
}

// ---------------------------------------------------------------------------
// Launch
// ---------------------------------------------------------------------------
template <int H, int C, int RELU>
static void run_layer(const float* x, int K,
                      const float* W, const float* asrc, const float* adst, const float* bias,
                      float* h, float* pas, float* pad,
                      const int* off, const int* csr_src, float* y) {
    constexpr int OC = H * C;
    dim3 ggrid((OC + 63) / 64, (NN + 127) / 128);
    gemm_kernel<<<ggrid, 256>>>(x, W, h, NN, K, OC);
    attn_node_kernel<H, C><<<(NN + 3) / 4, 128>>>(h, asrc, adst, pas, pad);
    constexpr int NPB = 128 / (OC / 4);
    aggregate_kernel<H, C, RELU><<<(NN + NPB - 1) / NPB, 128>>>(
        off, csr_src, h, pas, pad, bias, y);
}

extern "C" void kernel_launch(void* const* d_in, const int* in_sizes, int n_in,
                              void* d_out, int out_size) {
    const float* x = (const float*)d_in[0];
    const int* ei = (const int*)d_in[1];           // int32 (JAX x64 disabled)
    const float* W1 = (const float*)d_in[2];
    const float* as1 = (const float*)d_in[3];
    const float* ad1 = (const float*)d_in[4];
    const float* b1 = (const float*)d_in[5];
    const float* W2 = (const float*)d_in[6];
    const float* as2 = (const float*)d_in[7];
    const float* ad2 = (const float*)d_in[8];
    const float* b2 = (const float*)d_in[9];
    const float* W3 = (const float*)d_in[10];
    const float* as3 = (const float*)d_in[11];
    const float* ad3 = (const float*)d_in[12];
    const float* b3 = (const float*)d_in[13];
    int E = in_sizes[1] / 2;

    float *h, *y1, *y2, *pas, *pad;
    int *cnt, *off, *cursor, *csr_src;
    cudaGetSymbolAddress((void**)&h, g_h);
    cudaGetSymbolAddress((void**)&y1, g_y1);
    cudaGetSymbolAddress((void**)&y2, g_y2);
    cudaGetSymbolAddress((void**)&pas, g_as);
    cudaGetSymbolAddress((void**)&pad, g_ad);
    cudaGetSymbolAddress((void**)&cnt, g_cnt);
    cudaGetSymbolAddress((void**)&off, g_off);
    cudaGetSymbolAddress((void**)&cursor, g_cursor);
    cudaGetSymbolAddress((void**)&csr_src, g_csr_src);

    // Build CSR (group edges by destination) once; reused by all 3 layers.
    cudaMemsetAsync(cnt, 0, NN * sizeof(int));
    hist_kernel<<<(E + 255) / 256, 256>>>(ei, E, cnt);
    scan_kernel<<<1, 1024>>>(cnt, off, cursor);
    build_kernel<<<(E + 255) / 256, 256>>>(ei, E, cursor, csr_src);

    // Layer 1: in 128 -> 4 heads x 32, concat (128), relu
    run_layer<4, 32, 1>(x, 128, W1, as1, ad1, b1, h, pas, pad, off, csr_src, y1);
    // Layer 2: in 128 -> 2 heads x 32, concat (64), relu
    run_layer<2, 32, 1>(y1, 128, W2, as2, ad2, b2, h, pas, pad, off, csr_src, y2);
    // Layer 3: in 64 -> 1 head x 16, mean over 1 head == identity, no relu
    run_layer<1, 16, 0>(y2, 64, W3, as3, ad3, b3, h, pas, pad, off, csr_src, (float*)d_out);
}

// round 11
// speedup vs baseline: 1.0913x; 1.0261x over previous
#include <cuda_runtime.h>
#include <cstdint>

// ---------------------------------------------------------------------------
// ChainGNN: 3-layer GAT (heads 4/2/1, ch 32/32/16), N=50000, E=800000 (+self loops)
// CSR-fused design + 3xTF32 tensor-core GEMM (interleaved hi/lo, LDS.64 gathers)
// + CSR build overlapped with layer-1 GEMM via stream fork.
// ---------------------------------------------------------------------------

constexpr int NN = 50000;
constexpr int EMAX = 800000;
constexpr float SLOPE = 0.2f;

// Scratch (device globals; allocation is forbidden)
__device__ float g_h[NN * 128];       // post-GEMM features of current layer
__device__ float g_y1[NN * 128];      // layer1 activations
__device__ float g_y2[NN * 64];       // layer2 activations
__device__ float g_as[NN * 4];
__device__ float g_ad[NN * 4];
__device__ int   g_cnt[NN];
__device__ int   g_off[NN + 1];
__device__ int   g_cursor[NN];
__device__ int   g_csr_src[EMAX];

__device__ __forceinline__ float leaky(float v) { return v > 0.f ? v : SLOPE * v; }

__device__ __forceinline__ uint32_t f2tf32(float x) {
    uint32_t r;
    asm("cvt.rna.tf32.f32 %0, %1;" : "=r"(r) : "f"(x));
    return r;
}

#define MMA_TF32(C, A0, A1, A2, A3, B0, B1)                                   \
    asm volatile("mma.sync.aligned.m16n8k8.row.col.f32.tf32.tf32.f32 "        \
                 "{%0,%1,%2,%3}, {%4,%5,%6,%7}, {%8,%9}, {%0,%1,%2,%3};"      \
                 : "+f"(C[0]), "+f"(C[1]), "+f"(C[2]), "+f"(C[3])             \
                 : "r"(A0), "r"(A1), "r"(A2), "r"(A3), "r"(B0), "r"(B1))

// ---------------------------------------------------------------------------
// GEMM: O[n, outc] = X[n, K] @ W[K, outc].  3xTF32 tensor cores.
// Block 128x64, 256 threads (8 warps as 4Mx2N), warp tile 32x32, BK=16.
// hi/lo planes interleaved as uint2 -> every fragment gather is one LDS.64.
// Strides: Xs 20 uint2/row (words 8g+2c, conflict-free),
//          Ws 68 uint2/row (words 8c+2g, conflict-free).
// ---------------------------------------------------------------------------
__global__ void __launch_bounds__(256)
gemm_kernel(const float* __restrict__ X, const float* __restrict__ W,
            float* __restrict__ O, int n, int K, int outc) {
    constexpr int BM = 128, BK = 16;
    constexpr int XS = 20;   // Xs row stride in uint2 (16 + 4 pad)
    constexpr int WS = 68;   // Ws row stride in uint2 (64 + 4 pad)
    __shared__ uint2 Xs[BM * XS];      // 20 KB
    __shared__ uint2 Ws[BK * WS];      // 8.5 KB

    int t = threadIdx.x;
    int lane = t & 31;
    int wid = t >> 5;
    int warp_m = wid & 3;      // 0..3
    int warp_n = wid >> 2;     // 0..1
    int row0 = blockIdx.y * BM;
    int col0 = blockIdx.x * 64;

    float acc[2][4][4] = {};   // [mtile][ntile][frag]

    for (int kk = 0; kk < K; kk += BK) {
        // X tile: 128 rows x 16 k = 512 float4s, 2 per thread
        #pragma unroll
        for (int i = 0; i < 2; i++) {
            int f = t + i * 256;
            int m = f >> 2;
            int kseg = (f & 3) * 4;
            int gr = row0 + m;
            float4 v = make_float4(0.f, 0.f, 0.f, 0.f);
            if (gr < n)
                v = *reinterpret_cast<const float4*>(&X[(size_t)gr * K + kk + kseg]);
            float xv[4] = {v.x, v.y, v.z, v.w};
            #pragma unroll
            for (int j = 0; j < 4; j++) {
                uint32_t hi = f2tf32(xv[j]);
                float lo = xv[j] - __uint_as_float(hi);
                Xs[m * XS + kseg + j] = make_uint2(hi, f2tf32(lo));
            }
        }
        // W tile: 16 x 64 floats, 1 float4 per thread
        {
            int wr = t >> 4;
            int wc = (t & 15) * 4;
            int gc = col0 + wc;
            float4 v = make_float4(0.f, 0.f, 0.f, 0.f);
            if (gc < outc)
                v = *reinterpret_cast<const float4*>(&W[(size_t)(kk + wr) * outc + gc]);
            float wv[4] = {v.x, v.y, v.z, v.w};
            #pragma unroll
            for (int j = 0; j < 4; j++) {
                uint32_t hi = f2tf32(wv[j]);
                float lo = wv[j] - __uint_as_float(hi);
                Ws[wr * WS + wc + j] = make_uint2(hi, f2tf32(lo));
            }
        }
        __syncthreads();

        #pragma unroll
        for (int ks = 0; ks < 2; ks++) {
            int k0 = ks * 8;
            // A fragments for 2 M tiles: 4 LDS.64 each ({hi,lo} together)
            uint2 a[2][4];
            #pragma unroll
            for (int mt = 0; mt < 2; mt++) {
                int r = warp_m * 32 + mt * 16 + (lane >> 2);
                int c = k0 + (lane & 3);
                a[mt][0] = Xs[r * XS + c];
                a[mt][1] = Xs[(r + 8) * XS + c];
                a[mt][2] = Xs[r * XS + c + 4];
                a[mt][3] = Xs[(r + 8) * XS + c + 4];
            }
            // B fragments for 4 N tiles: 2 LDS.64 each
            uint2 b[4][2];
            #pragma unroll
            for (int nt = 0; nt < 4; nt++) {
                int cc = warp_n * 32 + nt * 8 + (lane >> 2);
                int rr = k0 + (lane & 3);
                b[nt][0] = Ws[rr * WS + cc];
                b[nt][1] = Ws[(rr + 4) * WS + cc];
            }
            #pragma unroll
            for (int mt = 0; mt < 2; mt++)
                #pragma unroll
                for (int nt = 0; nt < 4; nt++) {
                    MMA_TF32(acc[mt][nt], a[mt][0].x, a[mt][1].x, a[mt][2].x, a[mt][3].x,
                             b[nt][0].x, b[nt][1].x);                    // hi*hi
                    MMA_TF32(acc[mt][nt], a[mt][0].x, a[mt][1].x, a[mt][2].x, a[mt][3].x,
                             b[nt][0].y, b[nt][1].y);                    // hi*lo
                    MMA_TF32(acc[mt][nt], a[mt][0].y, a[mt][1].y, a[mt][2].y, a[mt][3].y,
                             b[nt][0].x, b[nt][1].x);                    // lo*hi
                }
        }
        __syncthreads();
    }

    // Epilogue: each fragment -> two float2 stores
    #pragma unroll
    for (int mt = 0; mt < 2; mt++)
        #pragma unroll
        for (int nt = 0; nt < 4; nt++) {
            int gr0 = row0 + warp_m * 32 + mt * 16 + (lane >> 2);
            int gc = col0 + warp_n * 32 + nt * 8 + (lane & 3) * 2;
            if (gc < outc) {
                if (gr0 < n)
                    *reinterpret_cast<float2*>(&O[(size_t)gr0 * outc + gc]) =
                        make_float2(acc[mt][nt][0], acc[mt][nt][1]);
                if (gr0 + 8 < n)
                    *reinterpret_cast<float2*>(&O[(size_t)(gr0 + 8) * outc + gc]) =
                        make_float2(acc[mt][nt][2], acc[mt][nt][3]);
            }
        }
}

// ---------------------------------------------------------------------------
// CSR build: histogram -> scan -> scatter
// ---------------------------------------------------------------------------
__global__ void hist_kernel(const int* __restrict__ ei, int E, int* __restrict__ cnt) {
    int e = blockIdx.x * blockDim.x + threadIdx.x;
    if (e < E) atomicAdd(&cnt[ei[E + e]], 1);
}

__global__ void scan_kernel(const int* __restrict__ cnt, int* __restrict__ off,
                            int* __restrict__ cursor) {
    __shared__ int part[1024];
    int t = threadIdx.x;
    constexpr int PER = (NN + 1023) / 1024;   // 49
    int base = t * PER;
    int sum = 0;
    for (int i = 0; i < PER; i++) {
        int idx = base + i;
        sum += (idx < NN) ? cnt[idx] : 0;
    }
    part[t] = sum;
    __syncthreads();
    for (int o = 1; o < 1024; o <<= 1) {
        int other = (t >= o) ? part[t - o] : 0;
        __syncthreads();
        part[t] += other;
        __syncthreads();
    }
    int run = part[t] - sum;
    for (int i = 0; i < PER; i++) {
        int idx = base + i;
        if (idx < NN) {
            off[idx] = run;
            cursor[idx] = run;
            run += cnt[idx];
        }
    }
    if (t == 1023) off[NN] = part[1023];
}

__global__ void build_kernel(const int* __restrict__ ei, int E,
                             int* __restrict__ cursor, int* __restrict__ csr_src) {
    int e = blockIdx.x * blockDim.x + threadIdx.x;
    if (e >= E) return;
    int d = ei[E + e];
    int pos = atomicAdd(&cursor[d], 1);
    csr_src[pos] = ei[e];
}

// ---------------------------------------------------------------------------
// Per-node attention scalars: as = <h, a_src>, ad = <h, a_dst>. One warp/node.
// ---------------------------------------------------------------------------
template <int H, int C>
__global__ void attn_node_kernel(const float* __restrict__ h,
                                 const float* __restrict__ a_src,
                                 const float* __restrict__ a_dst,
                                 float* __restrict__ as_, float* __restrict__ ad_) {
    int node = blockIdx.x * (blockDim.x >> 5) + (threadIdx.x >> 5);
    if (node >= NN) return;
    int lane = threadIdx.x & 31;
    const float* hr = h + (size_t)node * H * C;
    #pragma unroll
    for (int hh = 0; hh < H; hh++) {
        float s = 0.f, d = 0.f;
        for (int c = lane; c < C; c += 32) {
            float v = hr[hh * C + c];
            s += v * a_src[hh * C + c];
            d += v * a_dst[hh * C + c];
        }
        #pragma unroll
        for (int o = 16; o > 0; o >>= 1) {
            s += __shfl_xor_sync(0xffffffffu, s, o);
            d += __shfl_xor_sync(0xffffffffu, d, o);
        }
        if (lane == 0) {
            as_[node * H + hh] = s;
            ad_[node * H + hh] = d;
        }
    }
}

// ---------------------------------------------------------------------------
// Fused aggregation: per dst node, online-softmax over its in-edges + self loop.
// ---------------------------------------------------------------------------
template <int H, int C, int RELU>
__global__ void aggregate_kernel(const int* __restrict__ off,
                                 const int* __restrict__ csr_src,
                                 const float* __restrict__ h,
                                 const float* __restrict__ as_,
                                 const float* __restrict__ ad_,
                                 const float* __restrict__ bias,
                                 float* __restrict__ y) {
    constexpr int HC = H * C;
    constexpr int LPN = HC / 4;         // lanes per node
    constexpr int NPB = 128 / LPN;      // nodes per 128-thread block
    int t = threadIdx.x;
    int sub = t % LPN;
    int node = blockIdx.x * NPB + t / LPN;
    if (node >= NN) return;

    int fo = sub * 4;
    int hh = fo / C;
    float ad_d = ad_[node * H + hh];

    float m = leaky(as_[node * H + hh] + ad_d);
    float den = 1.f;
    float4 acc = *reinterpret_cast<const float4*>(&h[(size_t)node * HC + fo]);

    int beg = off[node], end = off[node + 1];
    #pragma unroll 2
    for (int idx = beg; idx < end; idx++) {
        int s = csr_src[idx];
        float l = leaky(as_[s * H + hh] + ad_d);
        float4 hv = *reinterpret_cast<const float4*>(&h[(size_t)s * HC + fo]);
        float nm = fmaxf(m, l);
        float scale = __expf(m - nm);
        float p = __expf(l - nm);
        acc.x = acc.x * scale + p * hv.x;
        acc.y = acc.y * scale + p * hv.y;
        acc.z = acc.z * scale + p * hv.z;
        acc.w = acc.w * scale + p * hv.w;
        den = den * scale + p;
        m = nm;
    }

    float iv = 1.f / (den + 1e-16f);
    float4 bv = *reinterpret_cast<const float4*>(&bias[fo]);
    float4 o;
    o.x = acc.x * iv + bv.x;
    o.y = acc.y * iv + bv.y;
    o.z = acc.z * iv + bv.z;
    o.w = acc.w * iv + bv.w;
    if (RELU) {
        o.x = fmaxf(o.x, 0.f); o.y = fmaxf(o.y, 0.f);
        o.z = fmaxf(o.z, 0.f); o.w = fmaxf(o.w, 0.f);
    }
    *reinterpret_cast<float4*>(&y[(size_t)node * HC + fo]) = o;
}

// ---------------------------------------------------------------------------
// Launch. CSR build forked onto a side stream, joined before aggregate_1.
// ---------------------------------------------------------------------------
template <int H, int C, int RELU>
static void run_layer(const float* x, int K,
                      const float* W, const float* asrc, const float* adst, const float* bias,
                      float* h, float* pas, float* pad,
                      const int* off, const int* csr_src, float* y) {
    constexpr int OC = H * C;
    dim3 ggrid((OC + 63) / 64, (NN + 127) / 128);
    gemm_kernel<<<ggrid, 256>>>(x, W, h, NN, K, OC);
    attn_node_kernel<H, C><<<(NN + 3) / 4, 128>>>(h, asrc, adst, pas, pad);
    constexpr int NPB = 128 / (OC / 4);
    aggregate_kernel<H, C, RELU><<<(NN + NPB - 1) / NPB, 128>>>(
        off, csr_src, h, pas, pad, bias, y);
}

struct SideRes {
    cudaStream_t s;
    cudaEvent_t ev_fork, ev_join;
    SideRes() {
        cudaStreamCreateWithFlags(&s, cudaStreamNonBlocking);
        cudaEventCreateWithFlags(&ev_fork, cudaEventDisableTiming);
        cudaEventCreateWithFlags(&ev_join, cudaEventDisableTiming);
    }
};

extern "C" void kernel_launch(void* const* d_in, const int* in_sizes, int n_in,
                              void* d_out, int out_size) {
    static SideRes R;   // created once; host-side resources only (no device mem)

    const float* x = (const float*)d_in[0];
    const int* ei = (const int*)d_in[1];           // int32 (JAX x64 disabled)
    const float* W1 = (const float*)d_in[2];
    const float* as1 = (const float*)d_in[3];
    const float* ad1 = (const float*)d_in[4];
    const float* b1 = (const float*)d_in[5];
    const float* W2 = (const float*)d_in[6];
    const float* as2 = (const float*)d_in[7];
    const float* ad2 = (const float*)d_in[8];
    const float* b2 = (const float*)d_in[9];
    const float* W3 = (const float*)d_in[10];
    const float* as3 = (const float*)d_in[11];
    const float* ad3 = (const float*)d_in[12];
    const float* b3 = (const float*)d_in[13];
    int E = in_sizes[1] / 2;

    float *h, *y1, *y2, *pas, *pad;
    int *cnt, *off, *cursor, *csr_src;
    cudaGetSymbolAddress((void**)&h, g_h);
    cudaGetSymbolAddress((void**)&y1, g_y1);
    cudaGetSymbolAddress((void**)&y2, g_y2);
    cudaGetSymbolAddress((void**)&pas, g_as);
    cudaGetSymbolAddress((void**)&pad, g_ad);
    cudaGetSymbolAddress((void**)&cnt, g_cnt);
    cudaGetSymbolAddress((void**)&off, g_off);
    cudaGetSymbolAddress((void**)&cursor, g_cursor);
    cudaGetSymbolAddress((void**)&csr_src, g_csr_src);

    // Fork: CSR build on side stream, concurrent with layer-1 GEMM + attn.
    cudaEventRecord(R.ev_fork, 0);
    cudaStreamWaitEvent(R.s, R.ev_fork, 0);
    cudaMemsetAsync(cnt, 0, NN * sizeof(int), R.s);
    hist_kernel<<<(E + 255) / 256, 256, 0, R.s>>>(ei, E, cnt);
    scan_kernel<<<1, 1024, 0, R.s>>>(cnt, off, cursor);
    build_kernel<<<(E + 255) / 256, 256, 0, R.s>>>(ei, E, cursor, csr_src);
    cudaEventRecord(R.ev_join, R.s);

    // Main stream: layer-1 GEMM + attention scalars (independent of CSR).
    {
        dim3 ggrid(2, (NN + 127) / 128);
        gemm_kernel<<<ggrid, 256>>>(x, W1, h, NN, 128, 128);
        attn_node_kernel<4, 32><<<(NN + 3) / 4, 128>>>(h, as1, ad1, pas, pad);
    }
    // Join: aggregation needs the CSR.
    cudaStreamWaitEvent(0, R.ev_join, 0);
    aggregate_kernel<4, 32, 1><<<(NN + 3) / 4, 128>>>(off, csr_src, h, pas, pad, b1, y1);

    // Layer 2: in 128 -> 2 heads x 32, concat (64), relu
    run_layer<2, 32, 1>(y1, 128, W2, as2, ad2, b2, h, pas, pad, off, csr_src, y2);
    // Layer 3: in 64 -> 1 head x 16, mean over 1 head == identity, no relu
    run_layer<1, 16, 0>(y2, 64, W3, as3, ad3, b3, h, pas, pad, off, csr_src, (float*)d_out);
}

// round 13
// speedup vs baseline: 1.2432x; 1.1392x over previous
#include <cuda_runtime.h>
#include <cstdint>

// ---------------------------------------------------------------------------
// ChainGNN: 3-layer GAT (heads 4/2/1, ch 32/32/16), N=50000, E=800000 (+self loops)
// R12: pre-decomposed tf32 hi/lo GEMM inputs (prep kernels + aggregate-epilogue
// fusion) + attention scalars fused into GEMM epilogue + CSR stream fork.
// ---------------------------------------------------------------------------

constexpr int NN = 50000;
constexpr int EMAX = 800000;
constexpr float SLOPE = 0.2f;

// Scratch (device globals; allocation is forbidden)
__device__ float g_h[NN * 128];       // post-GEMM features of current layer (fp32)
__device__ uint2 g_xd[NN * 128];      // decomposed layer-1 input
__device__ uint2 g_y1d[NN * 128];     // decomposed layer-1 output
__device__ uint2 g_y2d[NN * 64];      // decomposed layer-2 output
__device__ uint2 g_wd[16384 + 8192 + 1024];   // decomposed W1|W2|W3
__device__ float g_as[NN * 4];
__device__ float g_ad[NN * 4];
__device__ int   g_cnt[NN];
__device__ int   g_off[NN + 1];
__device__ int   g_cursor[NN];
__device__ int   g_csr_src[EMAX];

__device__ __forceinline__ float leaky(float v) { return v > 0.f ? v : SLOPE * v; }

__device__ __forceinline__ uint32_t f2tf32(float x) {
    uint32_t r;
    asm("cvt.rna.tf32.f32 %0, %1;" : "=r"(r) : "f"(x));
    return r;
}
__device__ __forceinline__ uint2 dec2(float v) {
    uint32_t hi = f2tf32(v);
    return make_uint2(hi, f2tf32(v - __uint_as_float(hi)));
}

#define MMA_TF32(C, A0, A1, A2, A3, B0, B1)                                   \
    asm volatile("mma.sync.aligned.m16n8k8.row.col.f32.tf32.tf32.f32 "        \
                 "{%0,%1,%2,%3}, {%4,%5,%6,%7}, {%8,%9}, {%0,%1,%2,%3};"      \
                 : "+f"(C[0]), "+f"(C[1]), "+f"(C[2]), "+f"(C[3])             \
                 : "r"(A0), "r"(A1), "r"(A2), "r"(A3), "r"(B0), "r"(B1))

// ---------------------------------------------------------------------------
// Prep: decompose fp32 -> interleaved {tf32_hi, tf32_lo}
// ---------------------------------------------------------------------------
__global__ void prep_x_kernel(const float* __restrict__ x, uint2* __restrict__ xd,
                              int total4) {
    int i = blockIdx.x * blockDim.x + threadIdx.x;
    if (i >= total4) return;
    float4 v = reinterpret_cast<const float4*>(x)[i];
    uint2 d0 = dec2(v.x), d1 = dec2(v.y), d2 = dec2(v.z), d3 = dec2(v.w);
    uint4* p = reinterpret_cast<uint4*>(xd + (size_t)i * 4);
    p[0] = make_uint4(d0.x, d0.y, d1.x, d1.y);
    p[1] = make_uint4(d2.x, d2.y, d3.x, d3.y);
}

__global__ void prep_w_kernel(const float* __restrict__ W1, const float* __restrict__ W2,
                              const float* __restrict__ W3, uint2* __restrict__ wd) {
    int i = blockIdx.x * blockDim.x + threadIdx.x;
    float v;
    if (i < 16384) v = W1[i];
    else if (i < 24576) v = W2[i - 16384];
    else if (i < 25600) v = W3[i - 24576];
    else return;
    wd[i] = dec2(v);
}

// ---------------------------------------------------------------------------
// GEMM + fused attention scalars.
// O[n, outc] = X[n, K] @ W[K, outc] via 3xTF32 mma.sync (inputs pre-decomposed).
// Block 128x64, 8 warps (4Mx2N), warp tile 32x32, BK=16.
// Epilogue: as_[row,h] = <O_row, a_src>, ad_[row,h] = <O_row, a_dst>
// computed from register fragments (CH = per-head channel count, 32 or 16).
// ---------------------------------------------------------------------------
template <int CH>
__global__ void __launch_bounds__(256)
gemm_attn_kernel(const uint2* __restrict__ Xd, const uint2* __restrict__ Wd,
                 float* __restrict__ O,
                 const float* __restrict__ a_src, const float* __restrict__ a_dst,
                 float* __restrict__ as_, float* __restrict__ ad_,
                 int n, int K, int outc, int H) {
    constexpr int BM = 128, BK = 16;
    constexpr int XS = 20;   // Xs row stride in uint2
    constexpr int WS = 68;   // Ws row stride in uint2
    __shared__ uint2 Xs[BM * XS];      // 20 KB
    __shared__ uint2 Ws[BK * WS];      // 8.5 KB

    int t = threadIdx.x;
    int lane = t & 31;
    int wid = t >> 5;
    int warp_m = wid & 3;      // 0..3
    int warp_n = wid >> 2;     // 0..1
    int row0 = blockIdx.y * BM;
    int col0 = blockIdx.x * 64;

    float acc[2][4][4] = {};   // [mtile][ntile][frag]

    for (int kk = 0; kk < K; kk += BK) {
        // X tile: 128 rows x 16 k uint2 = 1024 uint4 chunks, 4 per thread
        #pragma unroll
        for (int i = 0; i < 4; i++) {
            int q = t + i * 256;
            int m = q >> 3;
            int kp = (q & 7) * 2;
            int gr = row0 + m;
            uint4 v = make_uint4(0u, 0u, 0u, 0u);
            if (gr < n)
                v = *reinterpret_cast<const uint4*>(&Xd[(size_t)gr * K + kk + kp]);
            *reinterpret_cast<uint4*>(&Xs[m * XS + kp]) = v;
        }
        // W tile: 16 rows x 64 cols uint2 = 512 uint4 chunks, 2 per thread
        #pragma unroll
        for (int i = 0; i < 2; i++) {
            int q = t + i * 256;
            int wr = q >> 5;
            int wc = (q & 31) * 2;
            int gc = col0 + wc;
            uint4 v = make_uint4(0u, 0u, 0u, 0u);
            if (gc < outc)
                v = *reinterpret_cast<const uint4*>(&Wd[(size_t)(kk + wr) * outc + gc]);
            *reinterpret_cast<uint4*>(&Ws[wr * WS + wc]) = v;
        }
        __syncthreads();

        #pragma unroll
        for (int ks = 0; ks < 2; ks++) {
            int k0 = ks * 8;
            uint2 a[2][4];
            #pragma unroll
            for (int mt = 0; mt < 2; mt++) {
                int r = warp_m * 32 + mt * 16 + (lane >> 2);
                int c = k0 + (lane & 3);
                a[mt][0] = Xs[r * XS + c];
                a[mt][1] = Xs[(r + 8) * XS + c];
                a[mt][2] = Xs[r * XS + c + 4];
                a[mt][3] = Xs[(r + 8) * XS + c + 4];
            }
            uint2 b[4][2];
            #pragma unroll
            for (int nt = 0; nt < 4; nt++) {
                int cc = warp_n * 32 + nt * 8 + (lane >> 2);
                int rr = k0 + (lane & 3);
                b[nt][0] = Ws[rr * WS + cc];
                b[nt][1] = Ws[(rr + 4) * WS + cc];
            }
            #pragma unroll
            for (int mt = 0; mt < 2; mt++)
                #pragma unroll
                for (int nt = 0; nt < 4; nt++) {
                    MMA_TF32(acc[mt][nt], a[mt][0].x, a[mt][1].x, a[mt][2].x, a[mt][3].x,
                             b[nt][0].x, b[nt][1].x);                    // hi*hi
                    MMA_TF32(acc[mt][nt], a[mt][0].x, a[mt][1].x, a[mt][2].x, a[mt][3].x,
                             b[nt][0].y, b[nt][1].y);                    // hi*lo
                    MMA_TF32(acc[mt][nt], a[mt][0].y, a[mt][1].y, a[mt][2].y, a[mt][3].y,
                             b[nt][0].x, b[nt][1].x);                    // lo*hi
                }
        }
        __syncthreads();
    }

    // ---- O stores ----
    #pragma unroll
    for (int mt = 0; mt < 2; mt++)
        #pragma unroll
        for (int nt = 0; nt < 4; nt++) {
            int gr0 = row0 + warp_m * 32 + mt * 16 + (lane >> 2);
            int gc = col0 + warp_n * 32 + nt * 8 + (lane & 3) * 2;
            if (gc < outc) {
                if (gr0 < n)
                    *reinterpret_cast<float2*>(&O[(size_t)gr0 * outc + gc]) =
                        make_float2(acc[mt][nt][0], acc[mt][nt][1]);
                if (gr0 + 8 < n)
                    *reinterpret_cast<float2*>(&O[(size_t)(gr0 + 8) * outc + gc]) =
                        make_float2(acc[mt][nt][2], acc[mt][nt][3]);
            }
        }

    // ---- fused attention scalars ----
    int warp_col0 = col0 + warp_n * 32;
    #pragma unroll
    for (int mt = 0; mt < 2; mt++)
        #pragma unroll
        for (int half = 0; half < 2; half++) {
            float sg0 = 0.f, sg1 = 0.f, dg0 = 0.f, dg1 = 0.f;
            #pragma unroll
            for (int nt = 0; nt < 4; nt++) {
                int gc = warp_col0 + nt * 8 + (lane & 3) * 2;
                float a0 = 0.f, a1 = 0.f, b0 = 0.f, b1 = 0.f;
                if (gc < outc) {
                    a0 = a_src[gc]; a1 = a_src[gc + 1];
                    b0 = a_dst[gc]; b1 = a_dst[gc + 1];
                }
                float c0 = acc[mt][nt][half * 2 + 0];
                float c1 = acc[mt][nt][half * 2 + 1];
                if (nt < 2) { sg0 += c0 * a0 + c1 * a1; dg0 += c0 * b0 + c1 * b1; }
                else        { sg1 += c0 * a0 + c1 * a1; dg1 += c0 * b0 + c1 * b1; }
            }
            int row = row0 + warp_m * 32 + mt * 16 + (lane >> 2) + half * 8;
            if (CH == 32) {
                float s = sg0 + sg1, d = dg0 + dg1;
                s += __shfl_xor_sync(0xffffffffu, s, 1);
                s += __shfl_xor_sync(0xffffffffu, s, 2);
                d += __shfl_xor_sync(0xffffffffu, d, 1);
                d += __shfl_xor_sync(0xffffffffu, d, 2);
                if ((lane & 3) == 0 && row < n) {
                    int hh = warp_col0 >> 5;
                    as_[row * H + hh] = s;
                    ad_[row * H + hh] = d;
                }
            } else {  // CH == 16: two 16-col head groups per warp span
                sg0 += __shfl_xor_sync(0xffffffffu, sg0, 1);
                sg0 += __shfl_xor_sync(0xffffffffu, sg0, 2);
                dg0 += __shfl_xor_sync(0xffffffffu, dg0, 1);
                dg0 += __shfl_xor_sync(0xffffffffu, dg0, 2);
                sg1 += __shfl_xor_sync(0xffffffffu, sg1, 1);
                sg1 += __shfl_xor_sync(0xffffffffu, sg1, 2);
                dg1 += __shfl_xor_sync(0xffffffffu, dg1, 1);
                dg1 += __shfl_xor_sync(0xffffffffu, dg1, 2);
                if ((lane & 3) == 0 && row < n) {
                    if (warp_col0 < outc) {
                        int hh = warp_col0 >> 4;
                        as_[row * H + hh] = sg0;
                        ad_[row * H + hh] = dg0;
                    }
                    if (warp_col0 + 16 < outc) {
                        int hh = (warp_col0 + 16) >> 4;
                        as_[row * H + hh] = sg1;
                        ad_[row * H + hh] = dg1;
                    }
                }
            }
        }
}

// ---------------------------------------------------------------------------
// CSR build: histogram -> scan -> scatter
// ---------------------------------------------------------------------------
__global__ void hist_kernel(const int* __restrict__ ei, int E, int* __restrict__ cnt) {
    int e = blockIdx.x * blockDim.x + threadIdx.x;
    if (e < E) atomicAdd(&cnt[ei[E + e]], 1);
}

__global__ void scan_kernel(const int* __restrict__ cnt, int* __restrict__ off,
                            int* __restrict__ cursor) {
    __shared__ int part[1024];
    int t = threadIdx.x;
    constexpr int PER = (NN + 1023) / 1024;   // 49
    int base = t * PER;
    int sum = 0;
    for (int i = 0; i < PER; i++) {
        int idx = base + i;
        sum += (idx < NN) ? cnt[idx] : 0;
    }
    part[t] = sum;
    __syncthreads();
    for (int o = 1; o < 1024; o <<= 1) {
        int other = (t >= o) ? part[t - o] : 0;
        __syncthreads();
        part[t] += other;
        __syncthreads();
    }
    int run = part[t] - sum;
    for (int i = 0; i < PER; i++) {
        int idx = base + i;
        if (idx < NN) {
            off[idx] = run;
            cursor[idx] = run;
            run += cnt[idx];
        }
    }
    if (t == 1023) off[NN] = part[1023];
}

__global__ void build_kernel(const int* __restrict__ ei, int E,
                             int* __restrict__ cursor, int* __restrict__ csr_src) {
    int e = blockIdx.x * blockDim.x + threadIdx.x;
    if (e >= E) return;
    int d = ei[E + e];
    int pos = atomicAdd(&cursor[d], 1);
    csr_src[pos] = ei[e];
}

// ---------------------------------------------------------------------------
// Fused aggregation: per dst node, online-softmax over its in-edges + self loop.
// DECOMP=1: apply relu and emit decomposed uint2 {tf32 hi,lo} (next GEMM input).
// DECOMP=0: emit fp32 (final output), no relu.
// ---------------------------------------------------------------------------
template <int H, int C, int DECOMP>
__global__ void aggregate_kernel(const int* __restrict__ off,
                                 const int* __restrict__ csr_src,
                                 const float* __restrict__ h,
                                 const float* __restrict__ as_,
                                 const float* __restrict__ ad_,
                                 const float* __restrict__ bias,
                                 void* __restrict__ yout) {
    constexpr int HC = H * C;
    constexpr int LPN = HC / 4;         // lanes per node
    constexpr int NPB = 128 / LPN;      // nodes per 128-thread block
    int t = threadIdx.x;
    int sub = t % LPN;
    int node = blockIdx.x * NPB + t / LPN;
    if (node >= NN) return;

    int fo = sub * 4;
    int hh = fo / C;
    float ad_d = ad_[node * H + hh];

    float m = leaky(as_[node * H + hh] + ad_d);
    float den = 1.f;
    float4 acc = *reinterpret_cast<const float4*>(&h[(size_t)node * HC + fo]);

    int beg = off[node], end = off[node + 1];
    #pragma unroll 2
    for (int idx = beg; idx < end; idx++) {
        int s = csr_src[idx];
        float l = leaky(as_[s * H + hh] + ad_d);
        float4 hv = *reinterpret_cast<const float4*>(&h[(size_t)s * HC + fo]);
        float nm = fmaxf(m, l);
        float scale = __expf(m - nm);
        float p = __expf(l - nm);
        acc.x = acc.x * scale + p * hv.x;
        acc.y = acc.y * scale + p * hv.y;
        acc.z = acc.z * scale + p * hv.z;
        acc.w = acc.w * scale + p * hv.w;
        den = den * scale + p;
        m = nm;
    }

    float iv = 1.f / (den + 1e-16f);
    float4 bv = *reinterpret_cast<const float4*>(&bias[fo]);
    float4 o;
    o.x = acc.x * iv + bv.x;
    o.y = acc.y * iv + bv.y;
    o.z = acc.z * iv + bv.z;
    o.w = acc.w * iv + bv.w;
    if (DECOMP) {
        o.x = fmaxf(o.x, 0.f); o.y = fmaxf(o.y, 0.f);
        o.z = fmaxf(o.z, 0.f); o.w = fmaxf(o.w, 0.f);
        uint2 d0 = dec2(o.x), d1 = dec2(o.y), d2 = dec2(o.z), d3 = dec2(o.w);
        uint4* p = reinterpret_cast<uint4*>(
            reinterpret_cast<uint2*>(yout) + (size_t)node * HC + fo);
        p[0] = make_uint4(d0.x, d0.y, d1.x, d1.y);
        p[1] = make_uint4(d2.x, d2.y, d3.x, d3.y);
    } else {
        *reinterpret_cast<float4*>(
            reinterpret_cast<float*>(yout) + (size_t)node * HC + fo) = o;
    }
}

// ---------------------------------------------------------------------------
// Launch. CSR build forked onto a side stream, joined before aggregate_1.
// ---------------------------------------------------------------------------
struct SideRes {
    cudaStream_t s;
    cudaEvent_t ev_fork, ev_join;
    SideRes() {
        cudaStreamCreateWithFlags(&s, cudaStreamNonBlocking);
        cudaEventCreateWithFlags(&ev_fork, cudaEventDisableTiming);
        cudaEventCreateWithFlags(&ev_join, cudaEventDisableTiming);
    }
};

extern "C" void kernel_launch(void* const* d_in, const int* in_sizes, int n_in,
                              void* d_out, int out_size) {
    static SideRes R;   // host-side resources only (no device mem)

    const float* x = (const float*)d_in[0];
    const int* ei = (const int*)d_in[1];           // int32 (JAX x64 disabled)
    const float* W1 = (const float*)d_in[2];
    const float* as1 = (const float*)d_in[3];
    const float* ad1 = (const float*)d_in[4];
    const float* b1 = (const float*)d_in[5];
    const float* W2 = (const float*)d_in[6];
    const float* as2 = (const float*)d_in[7];
    const float* ad2 = (const float*)d_in[8];
    const float* b2 = (const float*)d_in[9];
    const float* W3 = (const float*)d_in[10];
    const float* as3 = (const float*)d_in[11];
    const float* ad3 = (const float*)d_in[12];
    const float* b3 = (const float*)d_in[13];
    int E = in_sizes[1] / 2;

    float *h, *pas, *pad;
    uint2 *xd, *y1d, *y2d, *wd;
    int *cnt, *off, *cursor, *csr_src;
    cudaGetSymbolAddress((void**)&h, g_h);
    cudaGetSymbolAddress((void**)&xd, g_xd);
    cudaGetSymbolAddress((void**)&y1d, g_y1d);
    cudaGetSymbolAddress((void**)&y2d, g_y2d);
    cudaGetSymbolAddress((void**)&wd, g_wd);
    cudaGetSymbolAddress((void**)&pas, g_as);
    cudaGetSymbolAddress((void**)&pad, g_ad);
    cudaGetSymbolAddress((void**)&cnt, g_cnt);
    cudaGetSymbolAddress((void**)&off, g_off);
    cudaGetSymbolAddress((void**)&cursor, g_cursor);
    cudaGetSymbolAddress((void**)&csr_src, g_csr_src);

    // Fork: CSR build on side stream, concurrent with prep + layer-1 GEMM.
    cudaEventRecord(R.ev_fork, 0);
    cudaStreamWaitEvent(R.s, R.ev_fork, 0);
    cudaMemsetAsync(cnt, 0, NN * sizeof(int), R.s);
    hist_kernel<<<(E + 255) / 256, 256, 0, R.s>>>(ei, E, cnt);
    scan_kernel<<<1, 1024, 0, R.s>>>(cnt, off, cursor);
    build_kernel<<<(E + 255) / 256, 256, 0, R.s>>>(ei, E, cursor, csr_src);
    cudaEventRecord(R.ev_join, R.s);

    // Main stream: prep decompositions.
    prep_x_kernel<<<(NN * 128 / 4 + 255) / 256, 256>>>(x, xd, NN * 128 / 4);
    prep_w_kernel<<<(25600 + 255) / 256, 256>>>(W1, W2, W3, wd);

    dim3 agg_grid1((NN + 3) / 4, 1);

    // Layer 1: in 128 -> 4 heads x 32, concat (128), relu
    gemm_attn_kernel<32><<<dim3(2, (NN + 127) / 128), 256>>>(
        xd, wd, h, as1, ad1, pas, pad, NN, 128, 128, 4);
    cudaStreamWaitEvent(0, R.ev_join, 0);   // aggregation needs the CSR
    aggregate_kernel<4, 32, 1><<<(NN + 3) / 4, 128>>>(
        off, csr_src, h, pas, pad, b1, y1d);

    // Layer 2: in 128 -> 2 heads x 32, concat (64), relu
    gemm_attn_kernel<32><<<dim3(1, (NN + 127) / 128), 256>>>(
        y1d, wd + 16384, h, as2, ad2, pas, pad, NN, 128, 64, 2);
    aggregate_kernel<2, 32, 1><<<(NN + 7) / 8, 128>>>(
        off, csr_src, h, pas, pad, b2, y2d);

    // Layer 3: in 64 -> 1 head x 16, mean over 1 head == identity, no relu
    gemm_attn_kernel<16><<<dim3(1, (NN + 127) / 128), 256>>>(
        y2d, wd + 24576, h, as3, ad3, pas, pad, NN, 64, 16, 1);
    aggregate_kernel<1, 16, 0><<<(NN + 31) / 32, 128>>>(
        off, csr_src, h, pas, pad, b3, d_out);
}

// round 14
// speedup vs baseline: 1.2592x; 1.0129x over previous
#include <cuda_runtime.h>
#include <cuda_fp16.h>
#include <cstdint>

// ---------------------------------------------------------------------------
// ChainGNN: 3-layer GAT (heads 4/2/1, ch 32/32/16), N=50000, E=800000 (+self loops)
// R14: message payload h stored as fp16 (half2) -> aggregate gather traffic
// halved. Attention logits stay fp32 (computed from GEMM register fragments).
// Pre-decomposed tf32 hi/lo GEMM inputs; CSR build on forked stream.
// ---------------------------------------------------------------------------

constexpr int NN = 50000;
constexpr int EMAX = 800000;
constexpr float SLOPE = 0.2f;

// Scratch (device globals; allocation is forbidden)
__device__ __half g_h[NN * 128];      // post-GEMM features, fp16 message payload
__device__ uint2 g_xd[NN * 128];      // decomposed layer-1 input
__device__ uint2 g_y1d[NN * 128];     // decomposed layer-1 output
__device__ uint2 g_y2d[NN * 64];      // decomposed layer-2 output
__device__ uint2 g_wd[16384 + 8192 + 1024];   // decomposed W1|W2|W3
__device__ float g_as[NN * 4];
__device__ float g_ad[NN * 4];
__device__ int   g_cnt[NN];
__device__ int   g_off[NN + 1];
__device__ int   g_cursor[NN];
__device__ int   g_csr_src[EMAX];

__device__ __forceinline__ float leaky(float v) { return v > 0.f ? v : SLOPE * v; }

__device__ __forceinline__ uint32_t f2tf32(float x) {
    uint32_t r;
    asm("cvt.rna.tf32.f32 %0, %1;" : "=r"(r) : "f"(x));
    return r;
}
__device__ __forceinline__ uint2 dec2(float v) {
    uint32_t hi = f2tf32(v);
    return make_uint2(hi, f2tf32(v - __uint_as_float(hi)));
}

#define MMA_TF32(C, A0, A1, A2, A3, B0, B1)                                   \
    asm volatile("mma.sync.aligned.m16n8k8.row.col.f32.tf32.tf32.f32 "        \
                 "{%0,%1,%2,%3}, {%4,%5,%6,%7}, {%8,%9}, {%0,%1,%2,%3};"      \
                 : "+f"(C[0]), "+f"(C[1]), "+f"(C[2]), "+f"(C[3])             \
                 : "r"(A0), "r"(A1), "r"(A2), "r"(A3), "r"(B0), "r"(B1))

// ---------------------------------------------------------------------------
// Prep: decompose fp32 -> interleaved {tf32_hi, tf32_lo}
// ---------------------------------------------------------------------------
__global__ void prep_x_kernel(const float* __restrict__ x, uint2* __restrict__ xd,
                              int total4) {
    int i = blockIdx.x * blockDim.x + threadIdx.x;
    if (i >= total4) return;
    float4 v = reinterpret_cast<const float4*>(x)[i];
    uint2 d0 = dec2(v.x), d1 = dec2(v.y), d2 = dec2(v.z), d3 = dec2(v.w);
    uint4* p = reinterpret_cast<uint4*>(xd + (size_t)i * 4);
    p[0] = make_uint4(d0.x, d0.y, d1.x, d1.y);
    p[1] = make_uint4(d2.x, d2.y, d3.x, d3.y);
}

__global__ void prep_w_kernel(const float* __restrict__ W1, const float* __restrict__ W2,
                              const float* __restrict__ W3, uint2* __restrict__ wd) {
    int i = blockIdx.x * blockDim.x + threadIdx.x;
    float v;
    if (i < 16384) v = W1[i];
    else if (i < 24576) v = W2[i - 16384];
    else if (i < 25600) v = W3[i - 24576];
    else return;
    wd[i] = dec2(v);
}

// ---------------------------------------------------------------------------
// GEMM + fused attention scalars.  O (fp16) = X @ W via 3xTF32 mma.sync.
// Block 128x64, 8 warps (4Mx2N), warp tile 32x32, BK=16.
// Epilogue: attention scalars from fp32 fragments (exact), then h as half2.
// ---------------------------------------------------------------------------
template <int CH>
__global__ void __launch_bounds__(256)
gemm_attn_kernel(const uint2* __restrict__ Xd, const uint2* __restrict__ Wd,
                 __half* __restrict__ O,
                 const float* __restrict__ a_src, const float* __restrict__ a_dst,
                 float* __restrict__ as_, float* __restrict__ ad_,
                 int n, int K, int outc, int H) {
    constexpr int BM = 128, BK = 16;
    constexpr int XS = 20;   // Xs row stride in uint2
    constexpr int WS = 68;   // Ws row stride in uint2
    __shared__ uint2 Xs[BM * XS];      // 20 KB
    __shared__ uint2 Ws[BK * WS];      // 8.5 KB

    int t = threadIdx.x;
    int lane = t & 31;
    int wid = t >> 5;
    int warp_m = wid & 3;      // 0..3
    int warp_n = wid >> 2;     // 0..1
    int row0 = blockIdx.y * BM;
    int col0 = blockIdx.x * 64;

    float acc[2][4][4] = {};   // [mtile][ntile][frag]

    for (int kk = 0; kk < K; kk += BK) {
        #pragma unroll
        for (int i = 0; i < 4; i++) {
            int q = t + i * 256;
            int m = q >> 3;
            int kp = (q & 7) * 2;
            int gr = row0 + m;
            uint4 v = make_uint4(0u, 0u, 0u, 0u);
            if (gr < n)
                v = *reinterpret_cast<const uint4*>(&Xd[(size_t)gr * K + kk + kp]);
            *reinterpret_cast<uint4*>(&Xs[m * XS + kp]) = v;
        }
        #pragma unroll
        for (int i = 0; i < 2; i++) {
            int q = t + i * 256;
            int wr = q >> 5;
            int wc = (q & 31) * 2;
            int gc = col0 + wc;
            uint4 v = make_uint4(0u, 0u, 0u, 0u);
            if (gc < outc)
                v = *reinterpret_cast<const uint4*>(&Wd[(size_t)(kk + wr) * outc + gc]);
            *reinterpret_cast<uint4*>(&Ws[wr * WS + wc]) = v;
        }
        __syncthreads();

        #pragma unroll
        for (int ks = 0; ks < 2; ks++) {
            int k0 = ks * 8;
            uint2 a[2][4];
            #pragma unroll
            for (int mt = 0; mt < 2; mt++) {
                int r = warp_m * 32 + mt * 16 + (lane >> 2);
                int c = k0 + (lane & 3);
                a[mt][0] = Xs[r * XS + c];
                a[mt][1] = Xs[(r + 8) * XS + c];
                a[mt][2] = Xs[r * XS + c + 4];
                a[mt][3] = Xs[(r + 8) * XS + c + 4];
            }
            uint2 b[4][2];
            #pragma unroll
            for (int nt = 0; nt < 4; nt++) {
                int cc = warp_n * 32 + nt * 8 + (lane >> 2);
                int rr = k0 + (lane & 3);
                b[nt][0] = Ws[rr * WS + cc];
                b[nt][1] = Ws[(rr + 4) * WS + cc];
            }
            #pragma unroll
            for (int mt = 0; mt < 2; mt++)
                #pragma unroll
                for (int nt = 0; nt < 4; nt++) {
                    MMA_TF32(acc[mt][nt], a[mt][0].x, a[mt][1].x, a[mt][2].x, a[mt][3].x,
                             b[nt][0].x, b[nt][1].x);                    // hi*hi
                    MMA_TF32(acc[mt][nt], a[mt][0].x, a[mt][1].x, a[mt][2].x, a[mt][3].x,
                             b[nt][0].y, b[nt][1].y);                    // hi*lo
                    MMA_TF32(acc[mt][nt], a[mt][0].y, a[mt][1].y, a[mt][2].y, a[mt][3].y,
                             b[nt][0].x, b[nt][1].x);                    // lo*hi
                }
        }
        __syncthreads();
    }

    // ---- O stores (fp16 half2) ----
    #pragma unroll
    for (int mt = 0; mt < 2; mt++)
        #pragma unroll
        for (int nt = 0; nt < 4; nt++) {
            int gr0 = row0 + warp_m * 32 + mt * 16 + (lane >> 2);
            int gc = col0 + warp_n * 32 + nt * 8 + (lane & 3) * 2;
            if (gc < outc) {
                if (gr0 < n)
                    *reinterpret_cast<__half2*>(&O[(size_t)gr0 * outc + gc]) =
                        __floats2half2_rn(acc[mt][nt][0], acc[mt][nt][1]);
                if (gr0 + 8 < n)
                    *reinterpret_cast<__half2*>(&O[(size_t)(gr0 + 8) * outc + gc]) =
                        __floats2half2_rn(acc[mt][nt][2], acc[mt][nt][3]);
            }
        }

    // ---- fused attention scalars (fp32 fragments, exact) ----
    int warp_col0 = col0 + warp_n * 32;
    #pragma unroll
    for (int mt = 0; mt < 2; mt++)
        #pragma unroll
        for (int half = 0; half < 2; half++) {
            float sg0 = 0.f, sg1 = 0.f, dg0 = 0.f, dg1 = 0.f;
            #pragma unroll
            for (int nt = 0; nt < 4; nt++) {
                int gc = warp_col0 + nt * 8 + (lane & 3) * 2;
                float a0 = 0.f, a1 = 0.f, b0 = 0.f, b1 = 0.f;
                if (gc < outc) {
                    a0 = a_src[gc]; a1 = a_src[gc + 1];
                    b0 = a_dst[gc]; b1 = a_dst[gc + 1];
                }
                float c0 = acc[mt][nt][half * 2 + 0];
                float c1 = acc[mt][nt][half * 2 + 1];
                if (nt < 2) { sg0 += c0 * a0 + c1 * a1; dg0 += c0 * b0 + c1 * b1; }
                else        { sg1 += c0 * a0 + c1 * a1; dg1 += c0 * b0 + c1 * b1; }
            }
            int row = row0 + warp_m * 32 + mt * 16 + (lane >> 2) + half * 8;
            if (CH == 32) {
                float s = sg0 + sg1, d = dg0 + dg1;
                s += __shfl_xor_sync(0xffffffffu, s, 1);
                s += __shfl_xor_sync(0xffffffffu, s, 2);
                d += __shfl_xor_sync(0xffffffffu, d, 1);
                d += __shfl_xor_sync(0xffffffffu, d, 2);
                if ((lane & 3) == 0 && row < n) {
                    int hh = warp_col0 >> 5;
                    as_[row * H + hh] = s;
                    ad_[row * H + hh] = d;
                }
            } else {  // CH == 16
                sg0 += __shfl_xor_sync(0xffffffffu, sg0, 1);
                sg0 += __shfl_xor_sync(0xffffffffu, sg0, 2);
                dg0 += __shfl_xor_sync(0xffffffffu, dg0, 1);
                dg0 += __shfl_xor_sync(0xffffffffu, dg0, 2);
                sg1 += __shfl_xor_sync(0xffffffffu, sg1, 1);
                sg1 += __shfl_xor_sync(0xffffffffu, sg1, 2);
                dg1 += __shfl_xor_sync(0xffffffffu, dg1, 1);
                dg1 += __shfl_xor_sync(0xffffffffu, dg1, 2);
                if ((lane & 3) == 0 && row < n) {
                    if (warp_col0 < outc) {
                        int hh = warp_col0 >> 4;
                        as_[row * H + hh] = sg0;
                        ad_[row * H + hh] = dg0;
                    }
                    if (warp_col0 + 16 < outc) {
                        int hh = (warp_col0 + 16) >> 4;
                        as_[row * H + hh] = sg1;
                        ad_[row * H + hh] = dg1;
                    }
                }
            }
        }
}

// ---------------------------------------------------------------------------
// CSR build: histogram -> scan -> scatter
// ---------------------------------------------------------------------------
__global__ void hist_kernel(const int* __restrict__ ei, int E, int* __restrict__ cnt) {
    int e = blockIdx.x * blockDim.x + threadIdx.x;
    if (e < E) atomicAdd(&cnt[ei[E + e]], 1);
}

__global__ void scan_kernel(const int* __restrict__ cnt, int* __restrict__ off,
                            int* __restrict__ cursor) {
    __shared__ int part[1024];
    int t = threadIdx.x;
    constexpr int PER = (NN + 1023) / 1024;   // 49
    int base = t * PER;
    int sum = 0;
    for (int i = 0; i < PER; i++) {
        int idx = base + i;
        sum += (idx < NN) ? cnt[idx] : 0;
    }
    part[t] = sum;
    __syncthreads();
    for (int o = 1; o < 1024; o <<= 1) {
        int other = (t >= o) ? part[t - o] : 0;
        __syncthreads();
        part[t] += other;
        __syncthreads();
    }
    int run = part[t] - sum;
    for (int i = 0; i < PER; i++) {
        int idx = base + i;
        if (idx < NN) {
            off[idx] = run;
            cursor[idx] = run;
            run += cnt[idx];
        }
    }
    if (t == 1023) off[NN] = part[1023];
}

__global__ void build_kernel(const int* __restrict__ ei, int E,
                             int* __restrict__ cursor, int* __restrict__ csr_src) {
    int e = blockIdx.x * blockDim.x + threadIdx.x;
    if (e >= E) return;
    int d = ei[E + e];
    int pos = atomicAdd(&cursor[d], 1);
    csr_src[pos] = ei[e];
}

// ---------------------------------------------------------------------------
// Fused aggregation: per dst node, online-softmax over its in-edges + self loop.
// h is fp16; each lane owns 4 channels (one uint2 = 2x half2 gather per edge).
// Softmax & accumulation in fp32.
// DECOMP=1: relu + emit decomposed uint2 (next GEMM input). DECOMP=0: fp32 out.
// ---------------------------------------------------------------------------
template <int H, int C, int DECOMP>
__global__ void aggregate_kernel(const int* __restrict__ off,
                                 const int* __restrict__ csr_src,
                                 const __half* __restrict__ h,
                                 const float* __restrict__ as_,
                                 const float* __restrict__ ad_,
                                 const float* __restrict__ bias,
                                 void* __restrict__ yout) {
    constexpr int HC = H * C;
    constexpr int LPN = HC / 4;         // lanes per node
    constexpr int NPB = 128 / LPN;      // nodes per 128-thread block
    int t = threadIdx.x;
    int sub = t % LPN;
    int node = blockIdx.x * NPB + t / LPN;
    if (node >= NN) return;

    int fo = sub * 4;
    int hh = fo / C;
    float ad_d = ad_[node * H + hh];

    float m = leaky(as_[node * H + hh] + ad_d);
    float den = 1.f;
    float ax, ay, az, aw;
    {
        uint2 raw = *reinterpret_cast<const uint2*>(&h[(size_t)node * HC + fo]);
        float2 v01 = __half22float2(*reinterpret_cast<__half2*>(&raw.x));
        float2 v23 = __half22float2(*reinterpret_cast<__half2*>(&raw.y));
        ax = v01.x; ay = v01.y; az = v23.x; aw = v23.y;
    }

    int beg = off[node], end = off[node + 1];
    #pragma unroll 2
    for (int idx = beg; idx < end; idx++) {
        int s = csr_src[idx];
        float l = leaky(as_[s * H + hh] + ad_d);
        uint2 raw = *reinterpret_cast<const uint2*>(&h[(size_t)s * HC + fo]);
        float2 v01 = __half22float2(*reinterpret_cast<__half2*>(&raw.x));
        float2 v23 = __half22float2(*reinterpret_cast<__half2*>(&raw.y));
        float nm = fmaxf(m, l);
        float scale = __expf(m - nm);
        float p = __expf(l - nm);
        ax = ax * scale + p * v01.x;
        ay = ay * scale + p * v01.y;
        az = az * scale + p * v23.x;
        aw = aw * scale + p * v23.y;
        den = den * scale + p;
        m = nm;
    }

    float iv = 1.f / (den + 1e-16f);
    float4 bv = *reinterpret_cast<const float4*>(&bias[fo]);
    float4 o;
    o.x = ax * iv + bv.x;
    o.y = ay * iv + bv.y;
    o.z = az * iv + bv.z;
    o.w = aw * iv + bv.w;
    if (DECOMP) {
        o.x = fmaxf(o.x, 0.f); o.y = fmaxf(o.y, 0.f);
        o.z = fmaxf(o.z, 0.f); o.w = fmaxf(o.w, 0.f);
        uint2 d0 = dec2(o.x), d1 = dec2(o.y), d2 = dec2(o.z), d3 = dec2(o.w);
        uint4* p = reinterpret_cast<uint4*>(
            reinterpret_cast<uint2*>(yout) + (size_t)node * HC + fo);
        p[0] = make_uint4(d0.x, d0.y, d1.x, d1.y);
        p[1] = make_uint4(d2.x, d2.y, d3.x, d3.y);
    } else {
        *reinterpret_cast<float4*>(
            reinterpret_cast<float*>(yout) + (size_t)node * HC + fo) = o;
    }
}

// ---------------------------------------------------------------------------
// Launch. CSR build forked onto a side stream, joined before aggregate_1.
// ---------------------------------------------------------------------------
struct SideRes {
    cudaStream_t s;
    cudaEvent_t ev_fork, ev_join;
    SideRes() {
        cudaStreamCreateWithFlags(&s, cudaStreamNonBlocking);
        cudaEventCreateWithFlags(&ev_fork, cudaEventDisableTiming);
        cudaEventCreateWithFlags(&ev_join, cudaEventDisableTiming);
    }
};

extern "C" void kernel_launch(void* const* d_in, const int* in_sizes, int n_in,
                              void* d_out, int out_size) {
    static SideRes R;   // host-side resources only (no device mem)

    const float* x = (const float*)d_in[0];
    const int* ei = (const int*)d_in[1];           // int32 (JAX x64 disabled)
    const float* W1 = (const float*)d_in[2];
    const float* as1 = (const float*)d_in[3];
    const float* ad1 = (const float*)d_in[4];
    const float* b1 = (const float*)d_in[5];
    const float* W2 = (const float*)d_in[6];
    const float* as2 = (const float*)d_in[7];
    const float* ad2 = (const float*)d_in[8];
    const float* b2 = (const float*)d_in[9];
    const float* W3 = (const float*)d_in[10];
    const float* as3 = (const float*)d_in[11];
    const float* ad3 = (const float*)d_in[12];
    const float* b3 = (const float*)d_in[13];
    int E = in_sizes[1] / 2;

    __half* h;
    float *pas, *pad;
    uint2 *xd, *y1d, *y2d, *wd;
    int *cnt, *off, *cursor, *csr_src;
    cudaGetSymbolAddress((void**)&h, g_h);
    cudaGetSymbolAddress((void**)&xd, g_xd);
    cudaGetSymbolAddress((void**)&y1d, g_y1d);
    cudaGetSymbolAddress((void**)&y2d, g_y2d);
    cudaGetSymbolAddress((void**)&wd, g_wd);
    cudaGetSymbolAddress((void**)&pas, g_as);
    cudaGetSymbolAddress((void**)&pad, g_ad);
    cudaGetSymbolAddress((void**)&cnt, g_cnt);
    cudaGetSymbolAddress((void**)&off, g_off);
    cudaGetSymbolAddress((void**)&cursor, g_cursor);
    cudaGetSymbolAddress((void**)&csr_src, g_csr_src);

    // Fork: CSR build on side stream, concurrent with prep + layer-1 GEMM.
    cudaEventRecord(R.ev_fork, 0);
    cudaStreamWaitEvent(R.s, R.ev_fork, 0);
    cudaMemsetAsync(cnt, 0, NN * sizeof(int), R.s);
    hist_kernel<<<(E + 255) / 256, 256, 0, R.s>>>(ei, E, cnt);
    scan_kernel<<<1, 1024, 0, R.s>>>(cnt, off, cursor);
    build_kernel<<<(E + 255) / 256, 256, 0, R.s>>>(ei, E, cursor, csr_src);
    cudaEventRecord(R.ev_join, R.s);

    // Main stream: prep decompositions.
    prep_x_kernel<<<(NN * 128 / 4 + 255) / 256, 256>>>(x, xd, NN * 128 / 4);
    prep_w_kernel<<<(25600 + 255) / 256, 256>>>(W1, W2, W3, wd);

    // Layer 1: in 128 -> 4 heads x 32, concat (128), relu
    gemm_attn_kernel<32><<<dim3(2, (NN + 127) / 128), 256>>>(
        xd, wd, h, as1, ad1, pas, pad, NN, 128, 128, 4);
    cudaStreamWaitEvent(0, R.ev_join, 0);   // aggregation needs the CSR
    aggregate_kernel<4, 32, 1><<<(NN + 3) / 4, 128>>>(
        off, csr_src, h, pas, pad, b1, y1d);

    // Layer 2: in 128 -> 2 heads x 32, concat (64), relu
    gemm_attn_kernel<32><<<dim3(1, (NN + 127) / 128), 256>>>(
        y1d, wd + 16384, h, as2, ad2, pas, pad, NN, 128, 64, 2);
    aggregate_kernel<2, 32, 1><<<(NN + 7) / 8, 128>>>(
        off, csr_src, h, pas, pad, b2, y2d);

    // Layer 3: in 64 -> 1 head x 16, mean over 1 head == identity, no relu
    gemm_attn_kernel<16><<<dim3(1, (NN + 127) / 128), 256>>>(
        y2d, wd + 24576, h, as3, ad3, pas, pad, NN, 64, 16, 1);
    aggregate_kernel<1, 16, 0><<<(NN + 31) / 32, 128>>>(
        off, csr_src, h, pas, pad, b3, d_out);
}

// round 15
// speedup vs baseline: 1.3364x; 1.0613x over previous
#include <cuda_runtime.h>
#include <cuda_fp16.h>
#include <cstdint>

// ---------------------------------------------------------------------------
// ChainGNN: 3-layer GAT (heads 4/2/1, ch 32/32/16), N=50000, E=800000 (+self loops)
// R15: aggregate rewritten -- 8 fp16 channels/lane (uint4 gathers), lazy
// max-rescale (flash-attn style), 4-edge prefetch batches. GEMM/CSR unchanged.
// ---------------------------------------------------------------------------

constexpr int NN = 50000;
constexpr int EMAX = 800000;
constexpr float SLOPE = 0.2f;

// Scratch (device globals; allocation is forbidden)
__device__ __half g_h[NN * 128];      // post-GEMM features, fp16 message payload
__device__ uint2 g_xd[NN * 128];      // decomposed layer-1 input
__device__ uint2 g_y1d[NN * 128];     // decomposed layer-1 output
__device__ uint2 g_y2d[NN * 64];      // decomposed layer-2 output
__device__ uint2 g_wd[16384 + 8192 + 1024];   // decomposed W1|W2|W3
__device__ float g_as[NN * 4];
__device__ float g_ad[NN * 4];
__device__ int   g_cnt[NN];
__device__ int   g_off[NN + 1];
__device__ int   g_cursor[NN];
__device__ int   g_csr_src[EMAX];

__device__ __forceinline__ float leaky(float v) { return v > 0.f ? v : SLOPE * v; }

__device__ __forceinline__ uint32_t f2tf32(float x) {
    uint32_t r;
    asm("cvt.rna.tf32.f32 %0, %1;" : "=r"(r) : "f"(x));
    return r;
}
__device__ __forceinline__ uint2 dec2(float v) {
    uint32_t hi = f2tf32(v);
    return make_uint2(hi, f2tf32(v - __uint_as_float(hi)));
}

#define MMA_TF32(C, A0, A1, A2, A3, B0, B1)                                   \
    asm volatile("mma.sync.aligned.m16n8k8.row.col.f32.tf32.tf32.f32 "        \
                 "{%0,%1,%2,%3}, {%4,%5,%6,%7}, {%8,%9}, {%0,%1,%2,%3};"      \
                 : "+f"(C[0]), "+f"(C[1]), "+f"(C[2]), "+f"(C[3])             \
                 : "r"(A0), "r"(A1), "r"(A2), "r"(A3), "r"(B0), "r"(B1))

// ---------------------------------------------------------------------------
// Prep: decompose fp32 -> interleaved {tf32_hi, tf32_lo}
// ---------------------------------------------------------------------------
__global__ void prep_x_kernel(const float* __restrict__ x, uint2* __restrict__ xd,
                              int total4) {
    int i = blockIdx.x * blockDim.x + threadIdx.x;
    if (i >= total4) return;
    float4 v = reinterpret_cast<const float4*>(x)[i];
    uint2 d0 = dec2(v.x), d1 = dec2(v.y), d2 = dec2(v.z), d3 = dec2(v.w);
    uint4* p = reinterpret_cast<uint4*>(xd + (size_t)i * 4);
    p[0] = make_uint4(d0.x, d0.y, d1.x, d1.y);
    p[1] = make_uint4(d2.x, d2.y, d3.x, d3.y);
}

__global__ void prep_w_kernel(const float* __restrict__ W1, const float* __restrict__ W2,
                              const float* __restrict__ W3, uint2* __restrict__ wd) {
    int i = blockIdx.x * blockDim.x + threadIdx.x;
    float v;
    if (i < 16384) v = W1[i];
    else if (i < 24576) v = W2[i - 16384];
    else if (i < 25600) v = W3[i - 24576];
    else return;
    wd[i] = dec2(v);
}

// ---------------------------------------------------------------------------
// GEMM + fused attention scalars.  O (fp16) = X @ W via 3xTF32 mma.sync.
// Block 128x64, 8 warps (4Mx2N), warp tile 32x32, BK=16.
// ---------------------------------------------------------------------------
template <int CH>
__global__ void __launch_bounds__(256)
gemm_attn_kernel(const uint2* __restrict__ Xd, const uint2* __restrict__ Wd,
                 __half* __restrict__ O,
                 const float* __restrict__ a_src, const float* __restrict__ a_dst,
                 float* __restrict__ as_, float* __restrict__ ad_,
                 int n, int K, int outc, int H) {
    constexpr int BM = 128, BK = 16;
    constexpr int XS = 20;   // Xs row stride in uint2
    constexpr int WS = 68;   // Ws row stride in uint2
    __shared__ uint2 Xs[BM * XS];      // 20 KB
    __shared__ uint2 Ws[BK * WS];      // 8.5 KB

    int t = threadIdx.x;
    int lane = t & 31;
    int wid = t >> 5;
    int warp_m = wid & 3;      // 0..3
    int warp_n = wid >> 2;     // 0..1
    int row0 = blockIdx.y * BM;
    int col0 = blockIdx.x * 64;

    float acc[2][4][4] = {};   // [mtile][ntile][frag]

    for (int kk = 0; kk < K; kk += BK) {
        #pragma unroll
        for (int i = 0; i < 4; i++) {
            int q = t + i * 256;
            int m = q >> 3;
            int kp = (q & 7) * 2;
            int gr = row0 + m;
            uint4 v = make_uint4(0u, 0u, 0u, 0u);
            if (gr < n)
                v = *reinterpret_cast<const uint4*>(&Xd[(size_t)gr * K + kk + kp]);
            *reinterpret_cast<uint4*>(&Xs[m * XS + kp]) = v;
        }
        #pragma unroll
        for (int i = 0; i < 2; i++) {
            int q = t + i * 256;
            int wr = q >> 5;
            int wc = (q & 31) * 2;
            int gc = col0 + wc;
            uint4 v = make_uint4(0u, 0u, 0u, 0u);
            if (gc < outc)
                v = *reinterpret_cast<const uint4*>(&Wd[(size_t)(kk + wr) * outc + gc]);
            *reinterpret_cast<uint4*>(&Ws[wr * WS + wc]) = v;
        }
        __syncthreads();

        #pragma unroll
        for (int ks = 0; ks < 2; ks++) {
            int k0 = ks * 8;
            uint2 a[2][4];
            #pragma unroll
            for (int mt = 0; mt < 2; mt++) {
                int r = warp_m * 32 + mt * 16 + (lane >> 2);
                int c = k0 + (lane & 3);
                a[mt][0] = Xs[r * XS + c];
                a[mt][1] = Xs[(r + 8) * XS + c];
                a[mt][2] = Xs[r * XS + c + 4];
                a[mt][3] = Xs[(r + 8) * XS + c + 4];
            }
            uint2 b[4][2];
            #pragma unroll
            for (int nt = 0; nt < 4; nt++) {
                int cc = warp_n * 32 + nt * 8 + (lane >> 2);
                int rr = k0 + (lane & 3);
                b[nt][0] = Ws[rr * WS + cc];
                b[nt][1] = Ws[(rr + 4) * WS + cc];
            }
            #pragma unroll
            for (int mt = 0; mt < 2; mt++)
                #pragma unroll
                for (int nt = 0; nt < 4; nt++) {
                    MMA_TF32(acc[mt][nt], a[mt][0].x, a[mt][1].x, a[mt][2].x, a[mt][3].x,
                             b[nt][0].x, b[nt][1].x);                    // hi*hi
                    MMA_TF32(acc[mt][nt], a[mt][0].x, a[mt][1].x, a[mt][2].x, a[mt][3].x,
                             b[nt][0].y, b[nt][1].y);                    // hi*lo
                    MMA_TF32(acc[mt][nt], a[mt][0].y, a[mt][1].y, a[mt][2].y, a[mt][3].y,
                             b[nt][0].x, b[nt][1].x);                    // lo*hi
                }
        }
        __syncthreads();
    }

    // ---- O stores (fp16 half2) ----
    #pragma unroll
    for (int mt = 0; mt < 2; mt++)
        #pragma unroll
        for (int nt = 0; nt < 4; nt++) {
            int gr0 = row0 + warp_m * 32 + mt * 16 + (lane >> 2);
            int gc = col0 + warp_n * 32 + nt * 8 + (lane & 3) * 2;
            if (gc < outc) {
                if (gr0 < n)
                    *reinterpret_cast<__half2*>(&O[(size_t)gr0 * outc + gc]) =
                        __floats2half2_rn(acc[mt][nt][0], acc[mt][nt][1]);
                if (gr0 + 8 < n)
                    *reinterpret_cast<__half2*>(&O[(size_t)(gr0 + 8) * outc + gc]) =
                        __floats2half2_rn(acc[mt][nt][2], acc[mt][nt][3]);
            }
        }

    // ---- fused attention scalars (fp32 fragments, exact) ----
    int warp_col0 = col0 + warp_n * 32;
    #pragma unroll
    for (int mt = 0; mt < 2; mt++)
        #pragma unroll
        for (int half = 0; half < 2; half++) {
            float sg0 = 0.f, sg1 = 0.f, dg0 = 0.f, dg1 = 0.f;
            #pragma unroll
            for (int nt = 0; nt < 4; nt++) {
                int gc = warp_col0 + nt * 8 + (lane & 3) * 2;
                float a0 = 0.f, a1 = 0.f, b0 = 0.f, b1 = 0.f;
                if (gc < outc) {
                    a0 = a_src[gc]; a1 = a_src[gc + 1];
                    b0 = a_dst[gc]; b1 = a_dst[gc + 1];
                }
                float c0 = acc[mt][nt][half * 2 + 0];
                float c1 = acc[mt][nt][half * 2 + 1];
                if (nt < 2) { sg0 += c0 * a0 + c1 * a1; dg0 += c0 * b0 + c1 * b1; }
                else        { sg1 += c0 * a0 + c1 * a1; dg1 += c0 * b0 + c1 * b1; }
            }
            int row = row0 + warp_m * 32 + mt * 16 + (lane >> 2) + half * 8;
            if (CH == 32) {
                float s = sg0 + sg1, d = dg0 + dg1;
                s += __shfl_xor_sync(0xffffffffu, s, 1);
                s += __shfl_xor_sync(0xffffffffu, s, 2);
                d += __shfl_xor_sync(0xffffffffu, d, 1);
                d += __shfl_xor_sync(0xffffffffu, d, 2);
                if ((lane & 3) == 0 && row < n) {
                    int hh = warp_col0 >> 5;
                    as_[row * H + hh] = s;
                    ad_[row * H + hh] = d;
                }
            } else {  // CH == 16
                sg0 += __shfl_xor_sync(0xffffffffu, sg0, 1);
                sg0 += __shfl_xor_sync(0xffffffffu, sg0, 2);
                dg0 += __shfl_xor_sync(0xffffffffu, dg0, 1);
                dg0 += __shfl_xor_sync(0xffffffffu, dg0, 2);
                sg1 += __shfl_xor_sync(0xffffffffu, sg1, 1);
                sg1 += __shfl_xor_sync(0xffffffffu, sg1, 2);
                dg1 += __shfl_xor_sync(0xffffffffu, dg1, 1);
                dg1 += __shfl_xor_sync(0xffffffffu, dg1, 2);
                if ((lane & 3) == 0 && row < n) {
                    if (warp_col0 < outc) {
                        int hh = warp_col0 >> 4;
                        as_[row * H + hh] = sg0;
                        ad_[row * H + hh] = dg0;
                    }
                    if (warp_col0 + 16 < outc) {
                        int hh = (warp_col0 + 16) >> 4;
                        as_[row * H + hh] = sg1;
                        ad_[row * H + hh] = dg1;
                    }
                }
            }
        }
}

// ---------------------------------------------------------------------------
// CSR build: histogram -> scan -> scatter
// ---------------------------------------------------------------------------
__global__ void hist_kernel(const int* __restrict__ ei, int E, int* __restrict__ cnt) {
    int e = blockIdx.x * blockDim.x + threadIdx.x;
    if (e < E) atomicAdd(&cnt[ei[E + e]], 1);
}

__global__ void scan_kernel(const int* __restrict__ cnt, int* __restrict__ off,
                            int* __restrict__ cursor) {
    __shared__ int part[1024];
    int t = threadIdx.x;
    constexpr int PER = (NN + 1023) / 1024;   // 49
    int base = t * PER;
    int sum = 0;
    for (int i = 0; i < PER; i++) {
        int idx = base + i;
        sum += (idx < NN) ? cnt[idx] : 0;
    }
    part[t] = sum;
    __syncthreads();
    for (int o = 1; o < 1024; o <<= 1) {
        int other = (t >= o) ? part[t - o] : 0;
        __syncthreads();
        part[t] += other;
        __syncthreads();
    }
    int run = part[t] - sum;
    for (int i = 0; i < PER; i++) {
        int idx = base + i;
        if (idx < NN) {
            off[idx] = run;
            cursor[idx] = run;
            run += cnt[idx];
        }
    }
    if (t == 1023) off[NN] = part[1023];
}

__global__ void build_kernel(const int* __restrict__ ei, int E,
                             int* __restrict__ cursor, int* __restrict__ csr_src) {
    int e = blockIdx.x * blockDim.x + threadIdx.x;
    if (e >= E) return;
    int d = ei[E + e];
    int pos = atomicAdd(&cursor[d], 1);
    csr_src[pos] = ei[e];
}

// ---------------------------------------------------------------------------
// Fused aggregation (R15): per dst node, online softmax with LAZY RESCALE.
// 8 fp16 channels per lane (uint4 gather), 4-edge prefetch batches.
// DECOMP=1: relu + emit decomposed uint2 (next GEMM input). DECOMP=0: fp32 out.
// ---------------------------------------------------------------------------
template <int H, int C, int DECOMP>
__global__ void aggregate_kernel(const int* __restrict__ off,
                                 const int* __restrict__ csr_src,
                                 const __half* __restrict__ h,
                                 const float* __restrict__ as_,
                                 const float* __restrict__ ad_,
                                 const float* __restrict__ bias,
                                 void* __restrict__ yout) {
    constexpr int HC = H * C;
    constexpr int LPN = HC / 8;         // lanes per node (8 channels each)
    constexpr int NPB = 128 / LPN;      // nodes per 128-thread block
    int t = threadIdx.x;
    int sub = t % LPN;
    int node = blockIdx.x * NPB + t / LPN;
    if (node >= NN) return;

    int fo = sub * 8;
    int hh = fo / C;
    float ad_d = ad_[node * H + hh];

    float m = leaky(as_[node * H + hh] + ad_d);   // self logit seeds max
    float den = 1.f;
    float acc[8];
    {
        uint4 raw = *reinterpret_cast<const uint4*>(&h[(size_t)node * HC + fo]);
        float2 v0 = __half22float2(*reinterpret_cast<__half2*>(&raw.x));
        float2 v1 = __half22float2(*reinterpret_cast<__half2*>(&raw.y));
        float2 v2 = __half22float2(*reinterpret_cast<__half2*>(&raw.z));
        float2 v3 = __half22float2(*reinterpret_cast<__half2*>(&raw.w));
        acc[0] = v0.x; acc[1] = v0.y; acc[2] = v1.x; acc[3] = v1.y;
        acc[4] = v2.x; acc[5] = v2.y; acc[6] = v3.x; acc[7] = v3.y;
    }

    int beg = off[node], end = off[node + 1];

    // merge one edge given its logit and raw payload
    auto merge = [&](float l, uint4 raw) {
        float p;
        if (l > m) {                      // rare: rescale history
            float r = __expf(m - l);
            den *= r;
            #pragma unroll
            for (int i = 0; i < 8; i++) acc[i] *= r;
            m = l;
            p = 1.f;
        } else {
            p = __expf(l - m);
        }
        den += p;
        float2 v0 = __half22float2(*reinterpret_cast<__half2*>(&raw.x));
        float2 v1 = __half22float2(*reinterpret_cast<__half2*>(&raw.y));
        float2 v2 = __half22float2(*reinterpret_cast<__half2*>(&raw.z));
        float2 v3 = __half22float2(*reinterpret_cast<__half2*>(&raw.w));
        acc[0] += p * v0.x; acc[1] += p * v0.y;
        acc[2] += p * v1.x; acc[3] += p * v1.y;
        acc[4] += p * v2.x; acc[5] += p * v2.y;
        acc[6] += p * v3.x; acc[7] += p * v3.y;
    };

    int idx = beg;
    for (; idx + 4 <= end; idx += 4) {
        int s0 = csr_src[idx + 0];
        int s1 = csr_src[idx + 1];
        int s2 = csr_src[idx + 2];
        int s3 = csr_src[idx + 3];
        float l0 = leaky(as_[s0 * H + hh] + ad_d);
        float l1 = leaky(as_[s1 * H + hh] + ad_d);
        float l2 = leaky(as_[s2 * H + hh] + ad_d);
        float l3 = leaky(as_[s3 * H + hh] + ad_d);
        uint4 r0 = *reinterpret_cast<const uint4*>(&h[(size_t)s0 * HC + fo]);
        uint4 r1 = *reinterpret_cast<const uint4*>(&h[(size_t)s1 * HC + fo]);
        uint4 r2 = *reinterpret_cast<const uint4*>(&h[(size_t)s2 * HC + fo]);
        uint4 r3 = *reinterpret_cast<const uint4*>(&h[(size_t)s3 * HC + fo]);
        merge(l0, r0); merge(l1, r1); merge(l2, r2); merge(l3, r3);
    }
    for (; idx < end; idx++) {
        int s = csr_src[idx];
        float l = leaky(as_[s * H + hh] + ad_d);
        uint4 r = *reinterpret_cast<const uint4*>(&h[(size_t)s * HC + fo]);
        merge(l, r);
    }

    float iv = 1.f / (den + 1e-16f);
    float o[8];
    {
        float4 b0 = *reinterpret_cast<const float4*>(&bias[fo]);
        float4 b1 = *reinterpret_cast<const float4*>(&bias[fo + 4]);
        o[0] = acc[0] * iv + b0.x; o[1] = acc[1] * iv + b0.y;
        o[2] = acc[2] * iv + b0.z; o[3] = acc[3] * iv + b0.w;
        o[4] = acc[4] * iv + b1.x; o[5] = acc[5] * iv + b1.y;
        o[6] = acc[6] * iv + b1.z; o[7] = acc[7] * iv + b1.w;
    }
    if (DECOMP) {
        #pragma unroll
        for (int i = 0; i < 8; i++) o[i] = fmaxf(o[i], 0.f);
        uint2* yp = reinterpret_cast<uint2*>(yout) + (size_t)node * HC + fo;
        uint4* p = reinterpret_cast<uint4*>(yp);
        #pragma unroll
        for (int q = 0; q < 4; q++) {
            uint2 da = dec2(o[q * 2]), db = dec2(o[q * 2 + 1]);
            p[q] = make_uint4(da.x, da.y, db.x, db.y);
        }
    } else {
        float* yp = reinterpret_cast<float*>(yout) + (size_t)node * HC + fo;
        *reinterpret_cast<float4*>(yp) = make_float4(o[0], o[1], o[2], o[3]);
        *reinterpret_cast<float4*>(yp + 4) = make_float4(o[4], o[5], o[6], o[7]);
    }
}

// ---------------------------------------------------------------------------
// Launch. CSR build forked onto a side stream, joined before aggregate_1.
// ---------------------------------------------------------------------------
struct SideRes {
    cudaStream_t s;
    cudaEvent_t ev_fork, ev_join;
    SideRes() {
        cudaStreamCreateWithFlags(&s, cudaStreamNonBlocking);
        cudaEventCreateWithFlags(&ev_fork, cudaEventDisableTiming);
        cudaEventCreateWithFlags(&ev_join, cudaEventDisableTiming);
    }
};

extern "C" void kernel_launch(void* const* d_in, const int* in_sizes, int n_in,
                              void* d_out, int out_size) {
    static SideRes R;   // host-side resources only (no device mem)

    const float* x = (const float*)d_in[0];
    const int* ei = (const int*)d_in[1];           // int32 (JAX x64 disabled)
    const float* W1 = (const float*)d_in[2];
    const float* as1 = (const float*)d_in[3];
    const float* ad1 = (const float*)d_in[4];
    const float* b1 = (const float*)d_in[5];
    const float* W2 = (const float*)d_in[6];
    const float* as2 = (const float*)d_in[7];
    const float* ad2 = (const float*)d_in[8];
    const float* b2 = (const float*)d_in[9];
    const float* W3 = (const float*)d_in[10];
    const float* as3 = (const float*)d_in[11];
    const float* ad3 = (const float*)d_in[12];
    const float* b3 = (const float*)d_in[13];
    int E = in_sizes[1] / 2;

    __half* h;
    float *pas, *pad;
    uint2 *xd, *y1d, *y2d, *wd;
    int *cnt, *off, *cursor, *csr_src;
    cudaGetSymbolAddress((void**)&h, g_h);
    cudaGetSymbolAddress((void**)&xd, g_xd);
    cudaGetSymbolAddress((void**)&y1d, g_y1d);
    cudaGetSymbolAddress((void**)&y2d, g_y2d);
    cudaGetSymbolAddress((void**)&wd, g_wd);
    cudaGetSymbolAddress((void**)&pas, g_as);
    cudaGetSymbolAddress((void**)&pad, g_ad);
    cudaGetSymbolAddress((void**)&cnt, g_cnt);
    cudaGetSymbolAddress((void**)&off, g_off);
    cudaGetSymbolAddress((void**)&cursor, g_cursor);
    cudaGetSymbolAddress((void**)&csr_src, g_csr_src);

    // Fork: CSR build on side stream, concurrent with prep + layer-1 GEMM.
    cudaEventRecord(R.ev_fork, 0);
    cudaStreamWaitEvent(R.s, R.ev_fork, 0);
    cudaMemsetAsync(cnt, 0, NN * sizeof(int), R.s);
    hist_kernel<<<(E + 255) / 256, 256, 0, R.s>>>(ei, E, cnt);
    scan_kernel<<<1, 1024, 0, R.s>>>(cnt, off, cursor);
    build_kernel<<<(E + 255) / 256, 256, 0, R.s>>>(ei, E, cursor, csr_src);
    cudaEventRecord(R.ev_join, R.s);

    // Main stream: prep decompositions.
    prep_x_kernel<<<(NN * 128 / 4 + 255) / 256, 256>>>(x, xd, NN * 128 / 4);
    prep_w_kernel<<<(25600 + 255) / 256, 256>>>(W1, W2, W3, wd);

    // Layer 1: in 128 -> 4 heads x 32, concat (128), relu
    gemm_attn_kernel<32><<<dim3(2, (NN + 127) / 128), 256>>>(
        xd, wd, h, as1, ad1, pas, pad, NN, 128, 128, 4);
    cudaStreamWaitEvent(0, R.ev_join, 0);   // aggregation needs the CSR
    aggregate_kernel<4, 32, 1><<<(NN + 7) / 8, 128>>>(
        off, csr_src, h, pas, pad, b1, y1d);

    // Layer 2: in 128 -> 2 heads x 32, concat (64), relu
    gemm_attn_kernel<32><<<dim3(1, (NN + 127) / 128), 256>>>(
        y1d, wd + 16384, h, as2, ad2, pas, pad, NN, 128, 64, 2);
    aggregate_kernel<2, 32, 1><<<(NN + 15) / 16, 128>>>(
        off, csr_src, h, pas, pad, b2, y2d);

    // Layer 3: in 64 -> 1 head x 16, mean over 1 head == identity, no relu
    gemm_attn_kernel<16><<<dim3(1, (NN + 127) / 128), 256>>>(
        y2d, wd + 24576, h, as3, ad3, pas, pad, NN, 64, 16, 1);
    aggregate_kernel<1, 16, 0><<<(NN + 63) / 64, 128>>>(
        off, csr_src, h, pas, pad, b3, d_out);
}

// round 16
// speedup vs baseline: 1.6710x; 1.2504x over previous
#include <cuda_runtime.h>
#include <cuda_fp16.h>
#include <cstdint>

// ---------------------------------------------------------------------------
// ChainGNN: 3-layer GAT (heads 4/2/1, ch 32/32/16), N=50000, E=800000 (+self loops)
// R16: full fp16 datapath. GEMM = mma.sync.m16n8k16.f16 with fp32 accumulate;
// weights pre-transposed to [outc][K] fp16; aggregate emits half2 directly.
// Softmax/aggregation/attn-scalars remain fp32.
// ---------------------------------------------------------------------------

constexpr int NN = 50000;
constexpr int EMAX = 800000;
constexpr float SLOPE = 0.2f;

// Scratch (device globals; allocation is forbidden)
__device__ __half g_h[NN * 128];      // post-GEMM features (fp16)
__device__ __half g_xh[NN * 128];     // fp16 layer-1 input
__device__ __half g_y1h[NN * 128];    // fp16 layer-1 activations
__device__ __half g_y2h[NN * 64];     // fp16 layer-2 activations
__device__ __half g_wh[16384 + 8192 + 1024];  // transposed fp16 W1|W2|W3 ([outc][K])
__device__ float g_as[NN * 4];
__device__ float g_ad[NN * 4];
__device__ int   g_cnt[NN];
__device__ int   g_off[NN + 1];
__device__ int   g_cursor[NN];
__device__ int   g_csr_src[EMAX];

__device__ __forceinline__ float leaky(float v) { return v > 0.f ? v : SLOPE * v; }

#define MMA_F16(C, A0, A1, A2, A3, B0, B1)                                    \
    asm volatile("mma.sync.aligned.m16n8k16.row.col.f32.f16.f16.f32 "         \
                 "{%0,%1,%2,%3}, {%4,%5,%6,%7}, {%8,%9}, {%0,%1,%2,%3};"      \
                 : "+f"(C[0]), "+f"(C[1]), "+f"(C[2]), "+f"(C[3])             \
                 : "r"(A0), "r"(A1), "r"(A2), "r"(A3), "r"(B0), "r"(B1))

// ---------------------------------------------------------------------------
// Prep: x fp32 -> fp16 (8 elems per thread)
// ---------------------------------------------------------------------------
__global__ void prep_x_kernel(const float* __restrict__ x, __half* __restrict__ xh,
                              int total8) {
    int i = blockIdx.x * blockDim.x + threadIdx.x;
    if (i >= total8) return;
    float4 v0 = reinterpret_cast<const float4*>(x)[i * 2];
    float4 v1 = reinterpret_cast<const float4*>(x)[i * 2 + 1];
    __half2 h0 = __floats2half2_rn(v0.x, v0.y);
    __half2 h1 = __floats2half2_rn(v0.z, v0.w);
    __half2 h2 = __floats2half2_rn(v1.x, v1.y);
    __half2 h3 = __floats2half2_rn(v1.z, v1.w);
    reinterpret_cast<uint4*>(xh)[i] = make_uint4(
        *reinterpret_cast<uint32_t*>(&h0), *reinterpret_cast<uint32_t*>(&h1),
        *reinterpret_cast<uint32_t*>(&h2), *reinterpret_cast<uint32_t*>(&h3));
}

// W [K][outc] fp32 -> wh [outc][K] fp16 (transposed)
__global__ void prep_w_kernel(const float* __restrict__ W1, const float* __restrict__ W2,
                              const float* __restrict__ W3, __half* __restrict__ wh) {
    int i = blockIdx.x * blockDim.x + threadIdx.x;
    if (i < 16384) {                 // W1: K=128, outc=128
        int c = i & 127, k = i >> 7;
        wh[c * 128 + k] = __float2half_rn(W1[i]);
    } else if (i < 24576) {          // W2: K=128, outc=64
        int j = i - 16384;
        int c = j & 63, k = j >> 6;
        wh[16384 + c * 128 + k] = __float2half_rn(W2[j]);
    } else if (i < 25600) {          // W3: K=64, outc=16
        int j = i - 24576;
        int c = j & 15, k = j >> 4;
        wh[24576 + c * 64 + k] = __float2half_rn(W3[j]);
    }
}

// ---------------------------------------------------------------------------
// GEMM (fp16 in, fp32 accum) + fused attention scalars.
// O[n, outc] = X[n, K] @ W[K, outc], W given transposed as Wt[outc][K].
// Block 128x64, 8 warps (4Mx2N), warp tile 32x32, BK=32 (2 k-steps of 16).
// Shared: Xs [128][40] halves, Ws [64][40] halves (stride 40 -> conflict-free
// half2 fragment loads: word addr = row*20 + (lane&3), distinct mod 32).
// ---------------------------------------------------------------------------
template <int CH>
__global__ void __launch_bounds__(256)
gemm_attn_kernel(const __half* __restrict__ Xh, const __half* __restrict__ Wt,
                 __half* __restrict__ O,
                 const float* __restrict__ a_src, const float* __restrict__ a_dst,
                 float* __restrict__ as_, float* __restrict__ ad_,
                 int n, int K, int outc, int H) {
    constexpr int BM = 128, BN = 64, BK = 32;
    constexpr int XSTR = 40;   // halves per Xs row
    constexpr int WSTR = 40;   // halves per Ws row
    __shared__ __half Xs[BM * XSTR];   // 10 KB
    __shared__ __half Ws[BN * WSTR];   // 5 KB

    int t = threadIdx.x;
    int lane = t & 31;
    int wid = t >> 5;
    int warp_m = wid & 3;
    int warp_n = wid >> 2;
    int row0 = blockIdx.y * BM;
    int col0 = blockIdx.x * BN;

    float acc[2][4][4] = {};   // [mtile][ntile][frag]

    for (int kk = 0; kk < K; kk += BK) {
        // X tile: 128 rows x 32 halves = 512 uint4, 2 per thread
        #pragma unroll
        for (int i = 0; i < 2; i++) {
            int q = t + i * 256;
            int m = q >> 2;
            int kseg = (q & 3) * 8;
            int gr = row0 + m;
            uint4 v = make_uint4(0u, 0u, 0u, 0u);
            if (gr < n)
                v = *reinterpret_cast<const uint4*>(&Xh[(size_t)gr * K + kk + kseg]);
            *reinterpret_cast<uint4*>(&Xs[m * XSTR + kseg]) = v;
        }
        // W tile: 64 rows x 32 halves = 256 uint4, 1 per thread
        {
            int c = t >> 2;
            int kseg = (t & 3) * 8;
            int gc = col0 + c;
            uint4 v = make_uint4(0u, 0u, 0u, 0u);
            if (gc < outc)
                v = *reinterpret_cast<const uint4*>(&Wt[(size_t)gc * K + kk + kseg]);
            *reinterpret_cast<uint4*>(&Ws[c * WSTR + kseg]) = v;
        }
        __syncthreads();

        #pragma unroll
        for (int ks = 0; ks < 2; ks++) {
            int k0 = ks * 16;
            // A fragments: row-major m16k16, 4x .b32 per mtile
            uint32_t a[2][4];
            #pragma unroll
            for (int mt = 0; mt < 2; mt++) {
                int r = warp_m * 32 + mt * 16 + (lane >> 2);
                int c = k0 + (lane & 3) * 2;
                a[mt][0] = *reinterpret_cast<const uint32_t*>(&Xs[r * XSTR + c]);
                a[mt][1] = *reinterpret_cast<const uint32_t*>(&Xs[(r + 8) * XSTR + c]);
                a[mt][2] = *reinterpret_cast<const uint32_t*>(&Xs[r * XSTR + c + 8]);
                a[mt][3] = *reinterpret_cast<const uint32_t*>(&Xs[(r + 8) * XSTR + c + 8]);
            }
            // B fragments: col-major k16n8, 2x .b32 per ntile
            uint32_t b[4][2];
            #pragma unroll
            for (int nt = 0; nt < 4; nt++) {
                int cc = warp_n * 32 + nt * 8 + (lane >> 2);
                int rr = k0 + (lane & 3) * 2;
                b[nt][0] = *reinterpret_cast<const uint32_t*>(&Ws[cc * WSTR + rr]);
                b[nt][1] = *reinterpret_cast<const uint32_t*>(&Ws[cc * WSTR + rr + 8]);
            }
            #pragma unroll
            for (int mt = 0; mt < 2; mt++)
                #pragma unroll
                for (int nt = 0; nt < 4; nt++)
                    MMA_F16(acc[mt][nt], a[mt][0], a[mt][1], a[mt][2], a[mt][3],
                            b[nt][0], b[nt][1]);
        }
        __syncthreads();
    }

    // ---- O stores (fp16 half2) ----
    #pragma unroll
    for (int mt = 0; mt < 2; mt++)
        #pragma unroll
        for (int nt = 0; nt < 4; nt++) {
            int gr0 = row0 + warp_m * 32 + mt * 16 + (lane >> 2);
            int gc = col0 + warp_n * 32 + nt * 8 + (lane & 3) * 2;
            if (gc < outc) {
                if (gr0 < n)
                    *reinterpret_cast<__half2*>(&O[(size_t)gr0 * outc + gc]) =
                        __floats2half2_rn(acc[mt][nt][0], acc[mt][nt][1]);
                if (gr0 + 8 < n)
                    *reinterpret_cast<__half2*>(&O[(size_t)(gr0 + 8) * outc + gc]) =
                        __floats2half2_rn(acc[mt][nt][2], acc[mt][nt][3]);
            }
        }

    // ---- fused attention scalars (fp32 fragments) ----
    int warp_col0 = col0 + warp_n * 32;
    #pragma unroll
    for (int mt = 0; mt < 2; mt++)
        #pragma unroll
        for (int half = 0; half < 2; half++) {
            float sg0 = 0.f, sg1 = 0.f, dg0 = 0.f, dg1 = 0.f;
            #pragma unroll
            for (int nt = 0; nt < 4; nt++) {
                int gc = warp_col0 + nt * 8 + (lane & 3) * 2;
                float a0 = 0.f, a1 = 0.f, b0 = 0.f, b1 = 0.f;
                if (gc < outc) {
                    a0 = a_src[gc]; a1 = a_src[gc + 1];
                    b0 = a_dst[gc]; b1 = a_dst[gc + 1];
                }
                float c0 = acc[mt][nt][half * 2 + 0];
                float c1 = acc[mt][nt][half * 2 + 1];
                if (nt < 2) { sg0 += c0 * a0 + c1 * a1; dg0 += c0 * b0 + c1 * b1; }
                else        { sg1 += c0 * a0 + c1 * a1; dg1 += c0 * b0 + c1 * b1; }
            }
            int row = row0 + warp_m * 32 + mt * 16 + (lane >> 2) + half * 8;
            if (CH == 32) {
                float s = sg0 + sg1, d = dg0 + dg1;
                s += __shfl_xor_sync(0xffffffffu, s, 1);
                s += __shfl_xor_sync(0xffffffffu, s, 2);
                d += __shfl_xor_sync(0xffffffffu, d, 1);
                d += __shfl_xor_sync(0xffffffffu, d, 2);
                if ((lane & 3) == 0 && row < n) {
                    int hh = warp_col0 >> 5;
                    as_[row * H + hh] = s;
                    ad_[row * H + hh] = d;
                }
            } else {  // CH == 16
                sg0 += __shfl_xor_sync(0xffffffffu, sg0, 1);
                sg0 += __shfl_xor_sync(0xffffffffu, sg0, 2);
                dg0 += __shfl_xor_sync(0xffffffffu, dg0, 1);
                dg0 += __shfl_xor_sync(0xffffffffu, dg0, 2);
                sg1 += __shfl_xor_sync(0xffffffffu, sg1, 1);
                sg1 += __shfl_xor_sync(0xffffffffu, sg1, 2);
                dg1 += __shfl_xor_sync(0xffffffffu, dg1, 1);
                dg1 += __shfl_xor_sync(0xffffffffu, dg1, 2);
                if ((lane & 3) == 0 && row < n) {
                    if (warp_col0 < outc) {
                        int hh = warp_col0 >> 4;
                        as_[row * H + hh] = sg0;
                        ad_[row * H + hh] = dg0;
                    }
                    if (warp_col0 + 16 < outc) {
                        int hh = (warp_col0 + 16) >> 4;
                        as_[row * H + hh] = sg1;
                        ad_[row * H + hh] = dg1;
                    }
                }
            }
        }
}

// ---------------------------------------------------------------------------
// CSR build: histogram -> scan -> scatter
// ---------------------------------------------------------------------------
__global__ void hist_kernel(const int* __restrict__ ei, int E, int* __restrict__ cnt) {
    int e = blockIdx.x * blockDim.x + threadIdx.x;
    if (e < E) atomicAdd(&cnt[ei[E + e]], 1);
}

__global__ void scan_kernel(const int* __restrict__ cnt, int* __restrict__ off,
                            int* __restrict__ cursor) {
    __shared__ int part[1024];
    int t = threadIdx.x;
    constexpr int PER = (NN + 1023) / 1024;   // 49
    int base = t * PER;
    int sum = 0;
    for (int i = 0; i < PER; i++) {
        int idx = base + i;
        sum += (idx < NN) ? cnt[idx] : 0;
    }
    part[t] = sum;
    __syncthreads();
    for (int o = 1; o < 1024; o <<= 1) {
        int other = (t >= o) ? part[t - o] : 0;
        __syncthreads();
        part[t] += other;
        __syncthreads();
    }
    int run = part[t] - sum;
    for (int i = 0; i < PER; i++) {
        int idx = base + i;
        if (idx < NN) {
            off[idx] = run;
            cursor[idx] = run;
            run += cnt[idx];
        }
    }
    if (t == 1023) off[NN] = part[1023];
}

__global__ void build_kernel(const int* __restrict__ ei, int E,
                             int* __restrict__ cursor, int* __restrict__ csr_src) {
    int e = blockIdx.x * blockDim.x + threadIdx.x;
    if (e >= E) return;
    int d = ei[E + e];
    int pos = atomicAdd(&cursor[d], 1);
    csr_src[pos] = ei[e];
}

// ---------------------------------------------------------------------------
// Fused aggregation: online softmax, lazy rescale, 8 fp16 channels/lane,
// 4-edge prefetch. OUT_HALF=1: relu + half2 out (next GEMM input).
// OUT_HALF=0: fp32 out (final).
// ---------------------------------------------------------------------------
template <int H, int C, int OUT_HALF>
__global__ void aggregate_kernel(const int* __restrict__ off,
                                 const int* __restrict__ csr_src,
                                 const __half* __restrict__ h,
                                 const float* __restrict__ as_,
                                 const float* __restrict__ ad_,
                                 const float* __restrict__ bias,
                                 void* __restrict__ yout) {
    constexpr int HC = H * C;
    constexpr int LPN = HC / 8;         // lanes per node (8 channels each)
    constexpr int NPB = 128 / LPN;      // nodes per 128-thread block
    int t = threadIdx.x;
    int sub = t % LPN;
    int node = blockIdx.x * NPB + t / LPN;
    if (node >= NN) return;

    int fo = sub * 8;
    int hh = fo / C;
    float ad_d = ad_[node * H + hh];

    float m = leaky(as_[node * H + hh] + ad_d);   // self logit seeds max
    float den = 1.f;
    float acc[8];
    {
        uint4 raw = *reinterpret_cast<const uint4*>(&h[(size_t)node * HC + fo]);
        float2 v0 = __half22float2(*reinterpret_cast<__half2*>(&raw.x));
        float2 v1 = __half22float2(*reinterpret_cast<__half2*>(&raw.y));
        float2 v2 = __half22float2(*reinterpret_cast<__half2*>(&raw.z));
        float2 v3 = __half22float2(*reinterpret_cast<__half2*>(&raw.w));
        acc[0] = v0.x; acc[1] = v0.y; acc[2] = v1.x; acc[3] = v1.y;
        acc[4] = v2.x; acc[5] = v2.y; acc[6] = v3.x; acc[7] = v3.y;
    }

    int beg = off[node], end = off[node + 1];

    auto merge = [&](float l, uint4 raw) {
        float p;
        if (l > m) {                      // rare: rescale history
            float r = __expf(m - l);
            den *= r;
            #pragma unroll
            for (int i = 0; i < 8; i++) acc[i] *= r;
            m = l;
            p = 1.f;
        } else {
            p = __expf(l - m);
        }
        den += p;
        float2 v0 = __half22float2(*reinterpret_cast<__half2*>(&raw.x));
        float2 v1 = __half22float2(*reinterpret_cast<__half2*>(&raw.y));
        float2 v2 = __half22float2(*reinterpret_cast<__half2*>(&raw.z));
        float2 v3 = __half22float2(*reinterpret_cast<__half2*>(&raw.w));
        acc[0] += p * v0.x; acc[1] += p * v0.y;
        acc[2] += p * v1.x; acc[3] += p * v1.y;
        acc[4] += p * v2.x; acc[5] += p * v2.y;
        acc[6] += p * v3.x; acc[7] += p * v3.y;
    };

    int idx = beg;
    for (; idx + 4 <= end; idx += 4) {
        int s0 = csr_src[idx + 0];
        int s1 = csr_src[idx + 1];
        int s2 = csr_src[idx + 2];
        int s3 = csr_src[idx + 3];
        float l0 = leaky(as_[s0 * H + hh] + ad_d);
        float l1 = leaky(as_[s1 * H + hh] + ad_d);
        float l2 = leaky(as_[s2 * H + hh] + ad_d);
        float l3 = leaky(as_[s3 * H + hh] + ad_d);
        uint4 r0 = *reinterpret_cast<const uint4*>(&h[(size_t)s0 * HC + fo]);
        uint4 r1 = *reinterpret_cast<const uint4*>(&h[(size_t)s1 * HC + fo]);
        uint4 r2 = *reinterpret_cast<const uint4*>(&h[(size_t)s2 * HC + fo]);
        uint4 r3 = *reinterpret_cast<const uint4*>(&h[(size_t)s3 * HC + fo]);
        merge(l0, r0); merge(l1, r1); merge(l2, r2); merge(l3, r3);
    }
    for (; idx < end; idx++) {
        int s = csr_src[idx];
        float l = leaky(as_[s * H + hh] + ad_d);
        uint4 r = *reinterpret_cast<const uint4*>(&h[(size_t)s * HC + fo]);
        merge(l, r);
    }

    float iv = 1.f / (den + 1e-16f);
    float o[8];
    {
        float4 b0 = *reinterpret_cast<const float4*>(&bias[fo]);
        float4 b1 = *reinterpret_cast<const float4*>(&bias[fo + 4]);
        o[0] = acc[0] * iv + b0.x; o[1] = acc[1] * iv + b0.y;
        o[2] = acc[2] * iv + b0.z; o[3] = acc[3] * iv + b0.w;
        o[4] = acc[4] * iv + b1.x; o[5] = acc[5] * iv + b1.y;
        o[6] = acc[6] * iv + b1.z; o[7] = acc[7] * iv + b1.w;
    }
    if (OUT_HALF) {
        #pragma unroll
        for (int i = 0; i < 8; i++) o[i] = fmaxf(o[i], 0.f);
        __half2 h0 = __floats2half2_rn(o[0], o[1]);
        __half2 h1 = __floats2half2_rn(o[2], o[3]);
        __half2 h2 = __floats2half2_rn(o[4], o[5]);
        __half2 h3 = __floats2half2_rn(o[6], o[7]);
        *reinterpret_cast<uint4*>(
            reinterpret_cast<__half*>(yout) + (size_t)node * HC + fo) =
            make_uint4(*reinterpret_cast<uint32_t*>(&h0),
                       *reinterpret_cast<uint32_t*>(&h1),
                       *reinterpret_cast<uint32_t*>(&h2),
                       *reinterpret_cast<uint32_t*>(&h3));
    } else {
        float* yp = reinterpret_cast<float*>(yout) + (size_t)node * HC + fo;
        *reinterpret_cast<float4*>(yp) = make_float4(o[0], o[1], o[2], o[3]);
        *reinterpret_cast<float4*>(yp + 4) = make_float4(o[4], o[5], o[6], o[7]);
    }
}

// ---------------------------------------------------------------------------
// Launch. CSR build forked onto a side stream, joined before aggregate_1.
// ---------------------------------------------------------------------------
struct SideRes {
    cudaStream_t s;
    cudaEvent_t ev_fork, ev_join;
    SideRes() {
        cudaStreamCreateWithFlags(&s, cudaStreamNonBlocking);
        cudaEventCreateWithFlags(&ev_fork, cudaEventDisableTiming);
        cudaEventCreateWithFlags(&ev_join, cudaEventDisableTiming);
    }
};

extern "C" void kernel_launch(void* const* d_in, const int* in_sizes, int n_in,
                              void* d_out, int out_size) {
    static SideRes R;   // host-side resources only (no device mem)

    const float* x = (const float*)d_in[0];
    const int* ei = (const int*)d_in[1];           // int32 (JAX x64 disabled)
    const float* W1 = (const float*)d_in[2];
    const float* as1 = (const float*)d_in[3];
    const float* ad1 = (const float*)d_in[4];
    const float* b1 = (const float*)d_in[5];
    const float* W2 = (const float*)d_in[6];
    const float* as2 = (const float*)d_in[7];
    const float* ad2 = (const float*)d_in[8];
    const float* b2 = (const float*)d_in[9];
    const float* W3 = (const float*)d_in[10];
    const float* as3 = (const float*)d_in[11];
    const float* ad3 = (const float*)d_in[12];
    const float* b3 = (const float*)d_in[13];
    int E = in_sizes[1] / 2;

    __half *h, *xh, *y1h, *y2h, *wh;
    float *pas, *pad;
    int *cnt, *off, *cursor, *csr_src;
    cudaGetSymbolAddress((void**)&h, g_h);
    cudaGetSymbolAddress((void**)&xh, g_xh);
    cudaGetSymbolAddress((void**)&y1h, g_y1h);
    cudaGetSymbolAddress((void**)&y2h, g_y2h);
    cudaGetSymbolAddress((void**)&wh, g_wh);
    cudaGetSymbolAddress((void**)&pas, g_as);
    cudaGetSymbolAddress((void**)&pad, g_ad);
    cudaGetSymbolAddress((void**)&cnt, g_cnt);
    cudaGetSymbolAddress((void**)&off, g_off);
    cudaGetSymbolAddress((void**)&cursor, g_cursor);
    cudaGetSymbolAddress((void**)&csr_src, g_csr_src);

    // Fork: CSR build on side stream, concurrent with prep + layer-1 GEMM.
    cudaEventRecord(R.ev_fork, 0);
    cudaStreamWaitEvent(R.s, R.ev_fork, 0);
    cudaMemsetAsync(cnt, 0, NN * sizeof(int), R.s);
    hist_kernel<<<(E + 255) / 256, 256, 0, R.s>>>(ei, E, cnt);
    scan_kernel<<<1, 1024, 0, R.s>>>(cnt, off, cursor);
    build_kernel<<<(E + 255) / 256, 256, 0, R.s>>>(ei, E, cursor, csr_src);
    cudaEventRecord(R.ev_join, R.s);

    // Main stream: prep conversions.
    prep_x_kernel<<<(NN * 128 / 8 + 255) / 256, 256>>>(x, xh, NN * 128 / 8);
    prep_w_kernel<<<(25600 + 255) / 256, 256>>>(W1, W2, W3, wh);

    // Layer 1: in 128 -> 4 heads x 32, concat (128), relu
    gemm_attn_kernel<32><<<dim3(2, (NN + 127) / 128), 256>>>(
        xh, wh, h, as1, ad1, pas, pad, NN, 128, 128, 4);
    cudaStreamWaitEvent(0, R.ev_join, 0);   // aggregation needs the CSR
    aggregate_kernel<4, 32, 1><<<(NN + 7) / 8, 128>>>(
        off, csr_src, h, pas, pad, b1, y1h);

    // Layer 2: in 128 -> 2 heads x 32, concat (64), relu
    gemm_attn_kernel<32><<<dim3(1, (NN + 127) / 128), 256>>>(
        y1h, wh + 16384, h, as2, ad2, pas, pad, NN, 128, 64, 2);
    aggregate_kernel<2, 32, 1><<<(NN + 15) / 16, 128>>>(
        off, csr_src, h, pas, pad, b2, y2h);

    // Layer 3: in 64 -> 1 head x 16, mean over 1 head == identity, no relu
    gemm_attn_kernel<16><<<dim3(1, (NN + 127) / 128), 256>>>(
        y2h, wh + 24576, h, as3, ad3, pas, pad, NN, 64, 16, 1);
    aggregate_kernel<1, 16, 0><<<(NN + 63) / 64, 128>>>(
        off, csr_src, h, pas, pad, b3, d_out);
}

// round 17
// speedup vs baseline: 1.7540x; 1.0496x over previous
#include <cuda_runtime.h>
#include <cuda_fp16.h>
#include <cstdint>

// ---------------------------------------------------------------------------
// ChainGNN: 3-layer GAT (heads 4/2/1, ch 32/32/16), N=50000, E=800000 (+self loops)
// R17: max-free softmax aggregate (exp rescaled by self logit; straight-line
// merge, no divergence) + vectorized CSR build. fp16 datapath otherwise as R16.
// ---------------------------------------------------------------------------

constexpr int NN = 50000;
constexpr int EMAX = 800000;
constexpr float SLOPE = 0.2f;

// Scratch (device globals; allocation is forbidden)
__device__ __half g_h[NN * 128];      // post-GEMM features (fp16)
__device__ __half g_xh[NN * 128];     // fp16 layer-1 input
__device__ __half g_y1h[NN * 128];    // fp16 layer-1 activations
__device__ __half g_y2h[NN * 64];     // fp16 layer-2 activations
__device__ __half g_wh[16384 + 8192 + 1024];  // transposed fp16 W1|W2|W3 ([outc][K])
__device__ float g_as[NN * 4];
__device__ float g_ad[NN * 4];
__device__ int   g_cnt[NN];
__device__ int   g_off[NN + 1];
__device__ int   g_cursor[NN];
__device__ int   g_csr_src[EMAX];

__device__ __forceinline__ float leaky(float v) { return v > 0.f ? v : SLOPE * v; }

#define MMA_F16(C, A0, A1, A2, A3, B0, B1)                                    \
    asm volatile("mma.sync.aligned.m16n8k16.row.col.f32.f16.f16.f32 "         \
                 "{%0,%1,%2,%3}, {%4,%5,%6,%7}, {%8,%9}, {%0,%1,%2,%3};"      \
                 : "+f"(C[0]), "+f"(C[1]), "+f"(C[2]), "+f"(C[3])             \
                 : "r"(A0), "r"(A1), "r"(A2), "r"(A3), "r"(B0), "r"(B1))

// ---------------------------------------------------------------------------
// Prep: x fp32 -> fp16 (8 elems per thread)
// ---------------------------------------------------------------------------
__global__ void prep_x_kernel(const float* __restrict__ x, __half* __restrict__ xh,
                              int total8) {
    int i = blockIdx.x * blockDim.x + threadIdx.x;
    if (i >= total8) return;
    float4 v0 = reinterpret_cast<const float4*>(x)[i * 2];
    float4 v1 = reinterpret_cast<const float4*>(x)[i * 2 + 1];
    __half2 h0 = __floats2half2_rn(v0.x, v0.y);
    __half2 h1 = __floats2half2_rn(v0.z, v0.w);
    __half2 h2 = __floats2half2_rn(v1.x, v1.y);
    __half2 h3 = __floats2half2_rn(v1.z, v1.w);
    reinterpret_cast<uint4*>(xh)[i] = make_uint4(
        *reinterpret_cast<uint32_t*>(&h0), *reinterpret_cast<uint32_t*>(&h1),
        *reinterpret_cast<uint32_t*>(&h2), *reinterpret_cast<uint32_t*>(&h3));
}

// W [K][outc] fp32 -> wh [outc][K] fp16 (transposed)
__global__ void prep_w_kernel(const float* __restrict__ W1, const float* __restrict__ W2,
                              const float* __restrict__ W3, __half* __restrict__ wh) {
    int i = blockIdx.x * blockDim.x + threadIdx.x;
    if (i < 16384) {                 // W1: K=128, outc=128
        int c = i & 127, k = i >> 7;
        wh[c * 128 + k] = __float2half_rn(W1[i]);
    } else if (i < 24576) {          // W2: K=128, outc=64
        int j = i - 16384;
        int c = j & 63, k = j >> 6;
        wh[16384 + c * 128 + k] = __float2half_rn(W2[j]);
    } else if (i < 25600) {          // W3: K=64, outc=16
        int j = i - 24576;
        int c = j & 15, k = j >> 4;
        wh[24576 + c * 64 + k] = __float2half_rn(W3[j]);
    }
}

// ---------------------------------------------------------------------------
// GEMM (fp16 in, fp32 accum) + fused attention scalars.
// ---------------------------------------------------------------------------
template <int CH>
__global__ void __launch_bounds__(256)
gemm_attn_kernel(const __half* __restrict__ Xh, const __half* __restrict__ Wt,
                 __half* __restrict__ O,
                 const float* __restrict__ a_src, const float* __restrict__ a_dst,
                 float* __restrict__ as_, float* __restrict__ ad_,
                 int n, int K, int outc, int H) {
    constexpr int BM = 128, BN = 64, BK = 32;
    constexpr int XSTR = 40;
    constexpr int WSTR = 40;
    __shared__ __half Xs[BM * XSTR];   // 10 KB
    __shared__ __half Ws[BN * WSTR];   // 5 KB

    int t = threadIdx.x;
    int lane = t & 31;
    int wid = t >> 5;
    int warp_m = wid & 3;
    int warp_n = wid >> 2;
    int row0 = blockIdx.y * BM;
    int col0 = blockIdx.x * BN;

    float acc[2][4][4] = {};

    for (int kk = 0; kk < K; kk += BK) {
        #pragma unroll
        for (int i = 0; i < 2; i++) {
            int q = t + i * 256;
            int m = q >> 2;
            int kseg = (q & 3) * 8;
            int gr = row0 + m;
            uint4 v = make_uint4(0u, 0u, 0u, 0u);
            if (gr < n)
                v = *reinterpret_cast<const uint4*>(&Xh[(size_t)gr * K + kk + kseg]);
            *reinterpret_cast<uint4*>(&Xs[m * XSTR + kseg]) = v;
        }
        {
            int c = t >> 2;
            int kseg = (t & 3) * 8;
            int gc = col0 + c;
            uint4 v = make_uint4(0u, 0u, 0u, 0u);
            if (gc < outc)
                v = *reinterpret_cast<const uint4*>(&Wt[(size_t)gc * K + kk + kseg]);
            *reinterpret_cast<uint4*>(&Ws[c * WSTR + kseg]) = v;
        }
        __syncthreads();

        #pragma unroll
        for (int ks = 0; ks < 2; ks++) {
            int k0 = ks * 16;
            uint32_t a[2][4];
            #pragma unroll
            for (int mt = 0; mt < 2; mt++) {
                int r = warp_m * 32 + mt * 16 + (lane >> 2);
                int c = k0 + (lane & 3) * 2;
                a[mt][0] = *reinterpret_cast<const uint32_t*>(&Xs[r * XSTR + c]);
                a[mt][1] = *reinterpret_cast<const uint32_t*>(&Xs[(r + 8) * XSTR + c]);
                a[mt][2] = *reinterpret_cast<const uint32_t*>(&Xs[r * XSTR + c + 8]);
                a[mt][3] = *reinterpret_cast<const uint32_t*>(&Xs[(r + 8) * XSTR + c + 8]);
            }
            uint32_t b[4][2];
            #pragma unroll
            for (int nt = 0; nt < 4; nt++) {
                int cc = warp_n * 32 + nt * 8 + (lane >> 2);
                int rr = k0 + (lane & 3) * 2;
                b[nt][0] = *reinterpret_cast<const uint32_t*>(&Ws[cc * WSTR + rr]);
                b[nt][1] = *reinterpret_cast<const uint32_t*>(&Ws[cc * WSTR + rr + 8]);
            }
            #pragma unroll
            for (int mt = 0; mt < 2; mt++)
                #pragma unroll
                for (int nt = 0; nt < 4; nt++)
                    MMA_F16(acc[mt][nt], a[mt][0], a[mt][1], a[mt][2], a[mt][3],
                            b[nt][0], b[nt][1]);
        }
        __syncthreads();
    }

    // ---- O stores (fp16 half2) ----
    #pragma unroll
    for (int mt = 0; mt < 2; mt++)
        #pragma unroll
        for (int nt = 0; nt < 4; nt++) {
            int gr0 = row0 + warp_m * 32 + mt * 16 + (lane >> 2);
            int gc = col0 + warp_n * 32 + nt * 8 + (lane & 3) * 2;
            if (gc < outc) {
                if (gr0 < n)
                    *reinterpret_cast<__half2*>(&O[(size_t)gr0 * outc + gc]) =
                        __floats2half2_rn(acc[mt][nt][0], acc[mt][nt][1]);
                if (gr0 + 8 < n)
                    *reinterpret_cast<__half2*>(&O[(size_t)(gr0 + 8) * outc + gc]) =
                        __floats2half2_rn(acc[mt][nt][2], acc[mt][nt][3]);
            }
        }

    // ---- fused attention scalars (fp32 fragments) ----
    int warp_col0 = col0 + warp_n * 32;
    #pragma unroll
    for (int mt = 0; mt < 2; mt++)
        #pragma unroll
        for (int half = 0; half < 2; half++) {
            float sg0 = 0.f, sg1 = 0.f, dg0 = 0.f, dg1 = 0.f;
            #pragma unroll
            for (int nt = 0; nt < 4; nt++) {
                int gc = warp_col0 + nt * 8 + (lane & 3) * 2;
                float a0 = 0.f, a1 = 0.f, b0 = 0.f, b1 = 0.f;
                if (gc < outc) {
                    a0 = a_src[gc]; a1 = a_src[gc + 1];
                    b0 = a_dst[gc]; b1 = a_dst[gc + 1];
                }
                float c0 = acc[mt][nt][half * 2 + 0];
                float c1 = acc[mt][nt][half * 2 + 1];
                if (nt < 2) { sg0 += c0 * a0 + c1 * a1; dg0 += c0 * b0 + c1 * b1; }
                else        { sg1 += c0 * a0 + c1 * a1; dg1 += c0 * b0 + c1 * b1; }
            }
            int row = row0 + warp_m * 32 + mt * 16 + (lane >> 2) + half * 8;
            if (CH == 32) {
                float s = sg0 + sg1, d = dg0 + dg1;
                s += __shfl_xor_sync(0xffffffffu, s, 1);
                s += __shfl_xor_sync(0xffffffffu, s, 2);
                d += __shfl_xor_sync(0xffffffffu, d, 1);
                d += __shfl_xor_sync(0xffffffffu, d, 2);
                if ((lane & 3) == 0 && row < n) {
                    int hh = warp_col0 >> 5;
                    as_[row * H + hh] = s;
                    ad_[row * H + hh] = d;
                }
            } else {  // CH == 16
                sg0 += __shfl_xor_sync(0xffffffffu, sg0, 1);
                sg0 += __shfl_xor_sync(0xffffffffu, sg0, 2);
                dg0 += __shfl_xor_sync(0xffffffffu, dg0, 1);
                dg0 += __shfl_xor_sync(0xffffffffu, dg0, 2);
                sg1 += __shfl_xor_sync(0xffffffffu, sg1, 1);
                sg1 += __shfl_xor_sync(0xffffffffu, sg1, 2);
                dg1 += __shfl_xor_sync(0xffffffffu, dg1, 1);
                dg1 += __shfl_xor_sync(0xffffffffu, dg1, 2);
                if ((lane & 3) == 0 && row < n) {
                    if (warp_col0 < outc) {
                        int hh = warp_col0 >> 4;
                        as_[row * H + hh] = sg0;
                        ad_[row * H + hh] = dg0;
                    }
                    if (warp_col0 + 16 < outc) {
                        int hh = (warp_col0 + 16) >> 4;
                        as_[row * H + hh] = sg1;
                        ad_[row * H + hh] = dg1;
                    }
                }
            }
        }
}

// ---------------------------------------------------------------------------
// CSR build: histogram -> scan -> scatter (4 edges per thread for MLP)
// ---------------------------------------------------------------------------
__global__ void hist_kernel(const int* __restrict__ ei, int E, int* __restrict__ cnt) {
    int q = blockIdx.x * blockDim.x + threadIdx.x;
    int e = q * 4;
    if (e + 4 <= E) {
        int4 d4 = *reinterpret_cast<const int4*>(&ei[E + e]);
        atomicAdd(&cnt[d4.x], 1);
        atomicAdd(&cnt[d4.y], 1);
        atomicAdd(&cnt[d4.z], 1);
        atomicAdd(&cnt[d4.w], 1);
    } else {
        for (; e < E; e++) atomicAdd(&cnt[ei[E + e]], 1);
    }
}

__global__ void scan_kernel(const int* __restrict__ cnt, int* __restrict__ off,
                            int* __restrict__ cursor) {
    __shared__ int part[1024];
    int t = threadIdx.x;
    constexpr int PER = (NN + 1023) / 1024;   // 49
    int base = t * PER;
    int sum = 0;
    for (int i = 0; i < PER; i++) {
        int idx = base + i;
        sum += (idx < NN) ? cnt[idx] : 0;
    }
    part[t] = sum;
    __syncthreads();
    for (int o = 1; o < 1024; o <<= 1) {
        int other = (t >= o) ? part[t - o] : 0;
        __syncthreads();
        part[t] += other;
        __syncthreads();
    }
    int run = part[t] - sum;
    for (int i = 0; i < PER; i++) {
        int idx = base + i;
        if (idx < NN) {
            off[idx] = run;
            cursor[idx] = run;
            run += cnt[idx];
        }
    }
    if (t == 1023) off[NN] = part[1023];
}

__global__ void build_kernel(const int* __restrict__ ei, int E,
                             int* __restrict__ cursor, int* __restrict__ csr_src) {
    int q = blockIdx.x * blockDim.x + threadIdx.x;
    int e = q * 4;
    if (e + 4 <= E) {
        int4 s4 = *reinterpret_cast<const int4*>(&ei[e]);
        int4 d4 = *reinterpret_cast<const int4*>(&ei[E + e]);
        int p0 = atomicAdd(&cursor[d4.x], 1);
        int p1 = atomicAdd(&cursor[d4.y], 1);
        int p2 = atomicAdd(&cursor[d4.z], 1);
        int p3 = atomicAdd(&cursor[d4.w], 1);
        csr_src[p0] = s4.x;
        csr_src[p1] = s4.y;
        csr_src[p2] = s4.z;
        csr_src[p3] = s4.w;
    } else {
        for (; e < E; e++) {
            int pos = atomicAdd(&cursor[ei[E + e]], 1);
            csr_src[pos] = ei[e];
        }
    }
}

// ---------------------------------------------------------------------------
// Fused aggregation (R17): MAX-FREE softmax. Logits rescaled by the node's
// self logit (exact softmax up to fp rounding; spreads << exp overflow range).
// Straight-line merge: no running max, no branch, no divergence.
// 8 fp16 channels/lane, 4-edge prefetch batches.
// ---------------------------------------------------------------------------
template <int H, int C, int OUT_HALF>
__global__ void aggregate_kernel(const int* __restrict__ off,
                                 const int* __restrict__ csr_src,
                                 const __half* __restrict__ h,
                                 const float* __restrict__ as_,
                                 const float* __restrict__ ad_,
                                 const float* __restrict__ bias,
                                 void* __restrict__ yout) {
    constexpr int HC = H * C;
    constexpr int LPN = HC / 8;         // lanes per node (8 channels each)
    constexpr int NPB = 128 / LPN;      // nodes per 128-thread block
    int t = threadIdx.x;
    int sub = t % LPN;
    int node = blockIdx.x * NPB + t / LPN;
    if (node >= NN) return;

    int fo = sub * 8;
    int hh = fo / C;
    float ad_d = ad_[node * H + hh];
    float lself = leaky(as_[node * H + hh] + ad_d);   // reference point

    float den = 1.f;    // self term: exp(0)
    float acc[8];
    {
        uint4 raw = *reinterpret_cast<const uint4*>(&h[(size_t)node * HC + fo]);
        float2 v0 = __half22float2(*reinterpret_cast<__half2*>(&raw.x));
        float2 v1 = __half22float2(*reinterpret_cast<__half2*>(&raw.y));
        float2 v2 = __half22float2(*reinterpret_cast<__half2*>(&raw.z));
        float2 v3 = __half22float2(*reinterpret_cast<__half2*>(&raw.w));
        acc[0] = v0.x; acc[1] = v0.y; acc[2] = v1.x; acc[3] = v1.y;
        acc[4] = v2.x; acc[5] = v2.y; acc[6] = v3.x; acc[7] = v3.y;
    }

    int beg = off[node], end = off[node + 1];

    auto merge = [&](float l, uint4 raw) {
        float p = __expf(l - lself);
        den += p;
        float2 v0 = __half22float2(*reinterpret_cast<__half2*>(&raw.x));
        float2 v1 = __half22float2(*reinterpret_cast<__half2*>(&raw.y));
        float2 v2 = __half22float2(*reinterpret_cast<__half2*>(&raw.z));
        float2 v3 = __half22float2(*reinterpret_cast<__half2*>(&raw.w));
        acc[0] += p * v0.x; acc[1] += p * v0.y;
        acc[2] += p * v1.x; acc[3] += p * v1.y;
        acc[4] += p * v2.x; acc[5] += p * v2.y;
        acc[6] += p * v3.x; acc[7] += p * v3.y;
    };

    int idx = beg;
    for (; idx + 4 <= end; idx += 4) {
        int s0 = csr_src[idx + 0];
        int s1 = csr_src[idx + 1];
        int s2 = csr_src[idx + 2];
        int s3 = csr_src[idx + 3];
        float l0 = leaky(as_[s0 * H + hh] + ad_d);
        float l1 = leaky(as_[s1 * H + hh] + ad_d);
        float l2 = leaky(as_[s2 * H + hh] + ad_d);
        float l3 = leaky(as_[s3 * H + hh] + ad_d);
        uint4 r0 = *reinterpret_cast<const uint4*>(&h[(size_t)s0 * HC + fo]);
        uint4 r1 = *reinterpret_cast<const uint4*>(&h[(size_t)s1 * HC + fo]);
        uint4 r2 = *reinterpret_cast<const uint4*>(&h[(size_t)s2 * HC + fo]);
        uint4 r3 = *reinterpret_cast<const uint4*>(&h[(size_t)s3 * HC + fo]);
        merge(l0, r0); merge(l1, r1); merge(l2, r2); merge(l3, r3);
    }
    for (; idx < end; idx++) {
        int s = csr_src[idx];
        float l = leaky(as_[s * H + hh] + ad_d);
        uint4 r = *reinterpret_cast<const uint4*>(&h[(size_t)s * HC + fo]);
        merge(l, r);
    }

    float iv = 1.f / (den + 1e-16f);
    float o[8];
    {
        float4 b0 = *reinterpret_cast<const float4*>(&bias[fo]);
        float4 b1 = *reinterpret_cast<const float4*>(&bias[fo + 4]);
        o[0] = acc[0] * iv + b0.x; o[1] = acc[1] * iv + b0.y;
        o[2] = acc[2] * iv + b0.z; o[3] = acc[3] * iv + b0.w;
        o[4] = acc[4] * iv + b1.x; o[5] = acc[5] * iv + b1.y;
        o[6] = acc[6] * iv + b1.z; o[7] = acc[7] * iv + b1.w;
    }
    if (OUT_HALF) {
        #pragma unroll
        for (int i = 0; i < 8; i++) o[i] = fmaxf(o[i], 0.f);
        __half2 h0 = __floats2half2_rn(o[0], o[1]);
        __half2 h1 = __floats2half2_rn(o[2], o[3]);
        __half2 h2 = __floats2half2_rn(o[4], o[5]);
        __half2 h3 = __floats2half2_rn(o[6], o[7]);
        *reinterpret_cast<uint4*>(
            reinterpret_cast<__half*>(yout) + (size_t)node * HC + fo) =
            make_uint4(*reinterpret_cast<uint32_t*>(&h0),
                       *reinterpret_cast<uint32_t*>(&h1),
                       *reinterpret_cast<uint32_t*>(&h2),
                       *reinterpret_cast<uint32_t*>(&h3));
    } else {
        float* yp = reinterpret_cast<float*>(yout) + (size_t)node * HC + fo;
        *reinterpret_cast<float4*>(yp) = make_float4(o[0], o[1], o[2], o[3]);
        *reinterpret_cast<float4*>(yp + 4) = make_float4(o[4], o[5], o[6], o[7]);
    }
}

// ---------------------------------------------------------------------------
// Launch. CSR build forked onto a side stream, joined before aggregate_1.
// ---------------------------------------------------------------------------
struct SideRes {
    cudaStream_t s;
    cudaEvent_t ev_fork, ev_join;
    SideRes() {
        cudaStreamCreateWithFlags(&s, cudaStreamNonBlocking);
        cudaEventCreateWithFlags(&ev_fork, cudaEventDisableTiming);
        cudaEventCreateWithFlags(&ev_join, cudaEventDisableTiming);
    }
};

extern "C" void kernel_launch(void* const* d_in, const int* in_sizes, int n_in,
                              void* d_out, int out_size) {
    static SideRes R;   // host-side resources only (no device mem)

    const float* x = (const float*)d_in[0];
    const int* ei = (const int*)d_in[1];           // int32 (JAX x64 disabled)
    const float* W1 = (const float*)d_in[2];
    const float* as1 = (const float*)d_in[3];
    const float* ad1 = (const float*)d_in[4];
    const float* b1 = (const float*)d_in[5];
    const float* W2 = (const float*)d_in[6];
    const float* as2 = (const float*)d_in[7];
    const float* ad2 = (const float*)d_in[8];
    const float* b2 = (const float*)d_in[9];
    const float* W3 = (const float*)d_in[10];
    const float* as3 = (const float*)d_in[11];
    const float* ad3 = (const float*)d_in[12];
    const float* b3 = (const float*)d_in[13];
    int E = in_sizes[1] / 2;

    __half *h, *xh, *y1h, *y2h, *wh;
    float *pas, *pad;
    int *cnt, *off, *cursor, *csr_src;
    cudaGetSymbolAddress((void**)&h, g_h);
    cudaGetSymbolAddress((void**)&xh, g_xh);
    cudaGetSymbolAddress((void**)&y1h, g_y1h);
    cudaGetSymbolAddress((void**)&y2h, g_y2h);
    cudaGetSymbolAddress((void**)&wh, g_wh);
    cudaGetSymbolAddress((void**)&pas, g_as);
    cudaGetSymbolAddress((void**)&pad, g_ad);
    cudaGetSymbolAddress((void**)&cnt, g_cnt);
    cudaGetSymbolAddress((void**)&off, g_off);
    cudaGetSymbolAddress((void**)&cursor, g_cursor);
    cudaGetSymbolAddress((void**)&csr_src, g_csr_src);

    // Fork: CSR build on side stream, concurrent with prep + layer-1 GEMM.
    cudaEventRecord(R.ev_fork, 0);
    cudaStreamWaitEvent(R.s, R.ev_fork, 0);
    cudaMemsetAsync(cnt, 0, NN * sizeof(int), R.s);
    hist_kernel<<<(E / 4 + 256) / 256, 256, 0, R.s>>>(ei, E, cnt);
    scan_kernel<<<1, 1024, 0, R.s>>>(cnt, off, cursor);
    build_kernel<<<(E / 4 + 256) / 256, 256, 0, R.s>>>(ei, E, cursor, csr_src);
    cudaEventRecord(R.ev_join, R.s);

    // Main stream: prep conversions.
    prep_x_kernel<<<(NN * 128 / 8 + 255) / 256, 256>>>(x, xh, NN * 128 / 8);
    prep_w_kernel<<<(25600 + 255) / 256, 256>>>(W1, W2, W3, wh);

    // Layer 1: in 128 -> 4 heads x 32, concat (128), relu
    gemm_attn_kernel<32><<<dim3(2, (NN + 127) / 128), 256>>>(
        xh, wh, h, as1, ad1, pas, pad, NN, 128, 128, 4);
    cudaStreamWaitEvent(0, R.ev_join, 0);   // aggregation needs the CSR
    aggregate_kernel<4, 32, 1><<<(NN + 7) / 8, 128>>>(
        off, csr_src, h, pas, pad, b1, y1h);

    // Layer 2: in 128 -> 2 heads x 32, concat (64), relu
    gemm_attn_kernel<32><<<dim3(1, (NN + 127) / 128), 256>>>(
        y1h, wh + 16384, h, as2, ad2, pas, pad, NN, 128, 64, 2);
    aggregate_kernel<2, 32, 1><<<(NN + 15) / 16, 128>>>(
        off, csr_src, h, pas, pad, b2, y2h);

    // Layer 3: in 64 -> 1 head x 16, mean over 1 head == identity, no relu
    gemm_attn_kernel<16><<<dim3(1, (NN + 127) / 128), 256>>>(
        y2h, wh + 24576, h, as3, ad3, pas, pad, NN, 64, 16, 1);
    aggregate_kernel<1, 16, 0><<<(NN + 63) / 64, 128>>>(
        off, csr_src, h, pas, pad, b3, d_out);
}